// round 13
// baseline (speedup 1.0000x reference)
#include <cuda_runtime.h>
#include <cuda_fp16.h>
#include <cstdint>

#define Nn 50000
#define Ee 500000
#define Tt 8
#define Fin 128
#define Dd 256
#define Hh 32
#define OUTC 64
#define TN (Tt*Nn)
#define LN_EPS 1e-5f
#define SNB 25
#define SCHUNK 2000

// ---------------- scratch ----------------
__device__ __half g_h[(size_t)TN*Dd];
__device__ __half g_x1h[(size_t)TN*Dd];
__device__ __half g_embh[(size_t)TN*Dd];
__device__ int    g_cnt[TN];
__device__ int    g_off[Tt*(Nn+1)];
__device__ int    g_cur[TN];
__device__ int    g_bsum[Tt*SNB];
__device__ int    g_srcs[Tt*Ee];
__device__ __half g_feats16[(size_t)TN*Fin];
__device__ __half g_W1h[Dd*Fin];
__device__ __half g_W2h[Dd*Dd];
__device__ __half g_Mh[Dd*Dd];
__device__ float  g_R[Dd*Dd];
__device__ __half g_Ph[OUTC*Dd];
__device__ float  g_c1[Dd];
__device__ float  g_c2[Dd];
__device__ float  g_c0;
__device__ float  g_tvec[Dd];
__device__ float  g_bconst[OUTC];
__device__ float  g_u[(size_t)Nn*Dd];
__device__ __half g_xbarh[(size_t)Nn*Dd];
__device__ float  g_logits[(size_t)Nn*OUTC];
__device__ float  g_psum[256*OUTC];
__device__ float  g_psq[256*OUTC];
__device__ float  g_mu[OUTC];
__device__ float  g_var[OUTC];

// ---------------- helpers ----------------
__device__ __forceinline__ float warp_sum(float v){
#pragma unroll
  for (int o=16;o;o>>=1) v += __shfl_xor_sync(0xffffffffu, v, o);
  return v;
}
__device__ __forceinline__ float warp_max(float v){
#pragma unroll
  for (int o=16;o;o>>=1) v = fmaxf(v, __shfl_xor_sync(0xffffffffu, v, o));
  return v;
}
__device__ __forceinline__ void cp16(uint32_t dst, const void* src, bool p){
  int sz = p ? 16 : 0;
  asm volatile("cp.async.cg.shared.global [%0], [%1], 16, %2;"
               :: "r"(dst), "l"(src), "r"(sz) : "memory");
}

// ---------------- fp32 -> fp16 convert ----------------
__global__ void f2h(const float* __restrict__ src, __half* __restrict__ dst, int n4){
  int i = blockIdx.x*256 + threadIdx.x;
  if (i >= n4) return;
  float4 v = *(const float4*)(src + (size_t)i*4);
  __half2 a = __float22half2_rn(make_float2(v.x, v.y));
  __half2 b = __float22half2_rn(make_float2(v.z, v.w));
  *(uint2*)(dst + (size_t)i*4) = make_uint2(*(uint32_t*)&a, *(uint32_t*)&b);
}

// =====================================================================
// FP16 tensor-core GEMM (m16n8k16, fp32 accum), 128x128 tile,
// cp.async 4-stage, .cg, single sync per k-tile.  (R11 config)
// =====================================================================
#define BM 128
#define BN 128
#define BK 32
#define SASH 40
#define NSTAGE 4
#define GEMM_SMEM (NSTAGE*(BM+BN)*SASH*2)

template<int OUTH>
__global__ __launch_bounds__(256) void gemm_hf(int Mr, int K, int NC,
    const __half* __restrict__ A, const __half* __restrict__ B,
    const float* __restrict__ bias, void* __restrict__ Cv)
{
  extern __shared__ __half smem[];
  __half* Asm = smem;
  __half* Bsm = smem + NSTAGE*BM*SASH;
  const int tid = threadIdx.x;
  const int brow = blockIdx.y*BM, bcol = blockIdx.x*BN;
  const int lane = tid & 31;
  const int wid  = tid >> 5;
  const int wm = (wid & 1)*64;
  const int wn = (wid >> 1)*32;

  float acc[4][4][4];
#pragma unroll
  for (int i=0;i<4;i++)
#pragma unroll
    for (int j=0;j<4;j++)
#pragma unroll
      for (int r=0;r<4;r++) acc[i][j][r]=0.f;

  int frow[2], fcol[2];
#pragma unroll
  for (int i=0;i<2;i++){ int f = tid + i*256; frow[i]=f>>2; fcol[i]=(f&3)*8; }

  uint32_t sA = (uint32_t)__cvta_generic_to_shared(Asm);
  uint32_t sB = (uint32_t)__cvta_generic_to_shared(Bsm);

  const int lr = lane & 7, lt = lane >> 3;
  const int a_row_off = lr + ((lt & 1) ? 8 : 0);
  const int a_col_off = (lt & 2) ? 8 : 0;
  const int b_row_off = lr + ((lt & 2) ? 8 : 0);
  const int b_col_off = (lt & 1) ? 8 : 0;

  const int KT = K/BK;

  auto issue = [&](int kt, int b){
    int k0 = kt*BK;
#pragma unroll
    for (int i=0;i<2;i++){
      int gr = brow + frow[i];
      bool pa = (gr < Mr);
      const __half* srca = A + (size_t)(pa?gr:0)*K + k0 + fcol[i];
      cp16(sA + (uint32_t)(b*BM*SASH + frow[i]*SASH + fcol[i])*2u, srca, pa);
      int gc = bcol + frow[i];
      bool pb = (gc < NC);
      const __half* srcb = B + (size_t)(pb?gc:0)*K + k0 + fcol[i];
      cp16(sB + (uint32_t)(b*BN*SASH + frow[i]*SASH + fcol[i])*2u, srcb, pb);
    }
    asm volatile("cp.async.commit_group;" ::: "memory");
  };

#pragma unroll
  for (int i=0;i<NSTAGE-1;i++)
    if (i < KT) issue(i, i);

  for (int kt=0; kt<KT; ++kt){
    if (kt+3 <= KT)      asm volatile("cp.async.wait_group 2;" ::: "memory");
    else if (kt+2 <= KT) asm volatile("cp.async.wait_group 1;" ::: "memory");
    else                 asm volatile("cp.async.wait_group 0;" ::: "memory");
    __syncthreads();
    if (kt+NSTAGE-1 < KT) issue(kt+NSTAGE-1, (kt+NSTAGE-1)%NSTAGE);

    int b = kt % NSTAGE;
    uint32_t baseA = sA + (uint32_t)(b*BM*SASH)*2u;
    uint32_t baseB = sB + (uint32_t)(b*BN*SASH)*2u;
#pragma unroll
    for (int ks=0; ks<2; ++ks){
      int k = ks*16;
      uint32_t a[4][4], bb[4][2];
#pragma unroll
      for (int mi=0; mi<4; ++mi){
        uint32_t addr = baseA + (uint32_t)((wm + mi*16 + a_row_off)*SASH + k + a_col_off)*2u;
        asm volatile("ldmatrix.sync.aligned.m8n8.x4.shared.b16 {%0,%1,%2,%3}, [%4];"
          : "=r"(a[mi][0]), "=r"(a[mi][1]), "=r"(a[mi][2]), "=r"(a[mi][3]) : "r"(addr));
      }
#pragma unroll
      for (int bj=0; bj<2; ++bj){
        uint32_t addr = baseB + (uint32_t)((wn + bj*16 + b_row_off)*SASH + k + b_col_off)*2u;
        uint32_t r0,r1,r2,r3;
        asm volatile("ldmatrix.sync.aligned.m8n8.x4.shared.b16 {%0,%1,%2,%3}, [%4];"
          : "=r"(r0), "=r"(r1), "=r"(r2), "=r"(r3) : "r"(addr));
        bb[bj*2+0][0]=r0; bb[bj*2+0][1]=r1;
        bb[bj*2+1][0]=r2; bb[bj*2+1][1]=r3;
      }
#pragma unroll
      for (int mi=0; mi<4; ++mi)
#pragma unroll
        for (int nj=0; nj<4; ++nj){
          asm volatile(
            "mma.sync.aligned.m16n8k16.row.col.f32.f16.f16.f32 "
            "{%0,%1,%2,%3}, {%4,%5,%6,%7}, {%8,%9}, {%0,%1,%2,%3};"
            : "+f"(acc[mi][nj][0]), "+f"(acc[mi][nj][1]),
              "+f"(acc[mi][nj][2]), "+f"(acc[mi][nj][3])
            : "r"(a[mi][0]), "r"(a[mi][1]), "r"(a[mi][2]), "r"(a[mi][3]),
              "r"(bb[nj][0]), "r"(bb[nj][1]));
        }
    }
  }

  const int g = lane >> 2, tg = lane & 3;
#pragma unroll
  for (int mi=0; mi<4; ++mi){
    int row0 = brow + wm + mi*16 + g;
    int row1 = row0 + 8;
#pragma unroll
    for (int nj=0; nj<4; ++nj){
      int col = bcol + wn + nj*8 + tg*2;
      if (col >= NC) continue;
      if (OUTH){
        __half* C = (__half*)Cv;
        __half2 v0 = __float22half2_rn(make_float2(acc[mi][nj][0], acc[mi][nj][1]));
        __half2 v1 = __float22half2_rn(make_float2(acc[mi][nj][2], acc[mi][nj][3]));
        if (row0 < Mr) *(__half2*)(C + (size_t)row0*NC + col) = v0;
        if (row1 < Mr) *(__half2*)(C + (size_t)row1*NC + col) = v1;
      } else {
        float* C = (float*)Cv;
        float b0 = bias ? bias[col]   : 0.f;
        float b1v= bias ? bias[col+1] : 0.f;
        if (row0 < Mr) *(float2*)(C + (size_t)row0*NC + col) = make_float2(acc[mi][nj][0]+b0, acc[mi][nj][1]+b1v);
        if (row1 < Mr) *(float2*)(C + (size_t)row1*NC + col) = make_float2(acc[mi][nj][2]+b0, acc[mi][nj][3]+b1v);
      }
    }
  }
}

// ---------------- tiled small-GEMM fold kernels ----------------
__global__ __launch_bounds__(256) void foldM(const float* __restrict__ Wqkv){
  __shared__ float As[16][64];
  __shared__ float Bs[16][64];
  int tx = threadIdx.x & 15, ty = threadIdx.x >> 4;
  int bj = blockIdx.y*64, bi = blockIdx.x*64;
  float acc[4][4] = {};
  int lkk = threadIdx.x >> 4;
  int lc4 = (threadIdx.x & 15)*4;
  for (int k0=0;k0<Dd;k0+=16){
    *(float4*)&As[lkk][lc4] = *(const float4*)&Wqkv[(size_t)(Dd+k0+lkk)*Dd + bj + lc4];
    *(float4*)&Bs[lkk][lc4] = *(const float4*)&Wqkv[(size_t)(k0+lkk)*Dd + bi + lc4];
    __syncthreads();
#pragma unroll
    for (int kk=0;kk<16;kk++){
      float ar[4], br[4];
#pragma unroll
      for (int r=0;r<4;r++) ar[r]=As[kk][ty*4+r];
#pragma unroll
      for (int c=0;c<4;c++) br[c]=Bs[kk][tx*4+c];
#pragma unroll
      for (int r=0;r<4;r++)
#pragma unroll
        for (int c=0;c<4;c++) acc[r][c]+=ar[r]*br[c];
    }
    __syncthreads();
  }
#pragma unroll
  for (int r=0;r<4;r++)
#pragma unroll
    for (int c=0;c<4;c++)
      g_Mh[(size_t)(bj+ty*4+r)*Dd + bi+tx*4+c] = __float2half(acc[r][c]);
}

template<int OH>
__global__ __launch_bounds__(256) void foldNN(const float* __restrict__ A,
                                              const float* __restrict__ B,
                                              void* __restrict__ Cv){
  __shared__ float As[64][17];
  __shared__ float Bs[16][64];
  int tx = threadIdx.x & 15, ty = threadIdx.x >> 4;
  int bi = blockIdx.y*64, bj = blockIdx.x*64;
  float acc[4][4] = {};
  int arow = threadIdx.x >> 2;
  int akc  = (threadIdx.x & 3)*4;
  int bkk  = threadIdx.x >> 4;
  int bc4  = (threadIdx.x & 15)*4;
  for (int k0=0;k0<Dd;k0+=16){
    float4 av = *(const float4*)&A[(size_t)(bi+arow)*Dd + k0 + akc];
    As[arow][akc+0]=av.x; As[arow][akc+1]=av.y; As[arow][akc+2]=av.z; As[arow][akc+3]=av.w;
    *(float4*)&Bs[bkk][bc4] = *(const float4*)&B[(size_t)(k0+bkk)*Dd + bj + bc4];
    __syncthreads();
#pragma unroll
    for (int kk=0;kk<16;kk++){
      float ar[4], br[4];
#pragma unroll
      for (int r=0;r<4;r++) ar[r]=As[ty*4+r][kk];
#pragma unroll
      for (int c=0;c<4;c++) br[c]=Bs[kk][tx*4+c];
#pragma unroll
      for (int r=0;r<4;r++)
#pragma unroll
        for (int c=0;c<4;c++) acc[r][c]+=ar[r]*br[c];
    }
    __syncthreads();
  }
#pragma unroll
  for (int r=0;r<4;r++)
#pragma unroll
    for (int c=0;c<4;c++){
      if (OH) ((__half*)Cv)[(size_t)(bi+ty*4+r)*Dd + bj+tx*4+c] = __float2half(acc[r][c]);
      else    ((float*)Cv)[(size_t)(bi+ty*4+r)*Dd + bj+tx*4+c] = acc[r][c];
    }
}

__global__ void foldVec(const float* __restrict__ Wqkv, const float* __restrict__ bqkv,
                        const float* __restrict__ Wo, const float* __restrict__ bo){
  int i = threadIdx.x;
  float s1=0.f, s2=0.f, tv=0.f;
  for (int k=0;k<Dd;k++){
    s1 += Wqkv[k*Dd+i]*bqkv[Dd+k];
    s2 += Wqkv[(Dd+k)*Dd+i]*bqkv[k];
    tv += Wo[i*Dd+k]*bqkv[2*Dd+k];
  }
  g_c1[i]=s1; g_c2[i]=s2; g_tvec[i]=tv+bo[i];
  if (i==0){
    float s0=0.f;
    for (int k=0;k<Dd;k++) s0 += bqkv[k]*bqkv[Dd+k];
    g_c0=s0;
  }
}
__global__ void foldBconst(const float* __restrict__ Wout, const float* __restrict__ bout){
  int o = threadIdx.x;
  if (o < OUTC){
    float b=0.f;
    for (int k=0;k<Dd;k++) b += Wout[o*Dd+k]*g_tvec[k];
    g_bconst[o]=b+bout[o];
  }
}

// ---------------- CSR build ----------------
__global__ void count_k(const int* __restrict__ ei){
  int idx = blockIdx.x*256 + threadIdx.x;
  if (idx >= Tt*Ee) return;
  int t = idx / Ee, e = idx - t*Ee;
  int dst = ei[(size_t)t*2*Ee + Ee + e];
  atomicAdd(&g_cnt[t*Nn + dst], 1);
}
__global__ void scan_p1(){
  int bid = blockIdx.x;
  int t = bid/SNB, b = bid - t*SNB;
  const int* cnt = g_cnt + t*Nn + b*SCHUNK;
  __shared__ int sh[256];
  int tid = threadIdx.x;
  int s = 0;
  if (tid < 250){
#pragma unroll
    for (int i=0;i<8;i++) s += cnt[tid*8+i];
  }
  sh[tid]=s; __syncthreads();
  for (int d=128; d; d>>=1){ if (tid<d) sh[tid]+=sh[tid+d]; __syncthreads(); }
  if (tid==0) g_bsum[bid]=sh[0];
}
__global__ void scan_p2(){
  int t = threadIdx.x;
  if (t < Tt){
    int run=0;
    for (int b=0;b<SNB;b++){
      int v = g_bsum[t*SNB+b];
      g_bsum[t*SNB+b] = run;
      run += v;
    }
    g_off[t*(Nn+1)+Nn] = run;
  }
}
__global__ void scan_p3(){
  int bid = blockIdx.x;
  int t = bid/SNB, b = bid - t*SNB;
  int base = t*Nn + b*SCHUNK;
  const int* cnt = g_cnt + base;
  int* off = g_off + t*(Nn+1) + b*SCHUNK;
  int* cur = g_cur + base;
  __shared__ int sh[256];
  int tid = threadIdx.x;
  int vals[8]; int s=0;
  if (tid < 250){
#pragma unroll
    for (int i=0;i<8;i++){ vals[i]=cnt[tid*8+i]; s+=vals[i]; }
  }
  sh[tid]=s; __syncthreads();
  for (int d=1; d<256; d<<=1){
    int v = (tid>=d)? sh[tid-d]:0;
    __syncthreads();
    sh[tid]+=v;
    __syncthreads();
  }
  int run = g_bsum[bid] + ((tid==0)?0:sh[tid-1]);
  if (tid < 250){
#pragma unroll
    for (int i=0;i<8;i++){
      off[tid*8+i]=run; cur[tid*8+i]=run; run += vals[i];
    }
  }
}
__global__ void scatter_k(const int* __restrict__ ei){
  int idx = blockIdx.x*256 + threadIdx.x;
  if (idx >= Tt*Ee) return;
  int t = idx / Ee, e = idx - t*Ee;
  int src = ei[(size_t)t*2*Ee + e];
  int dst = ei[(size_t)t*2*Ee + Ee + e];
  int p = atomicAdd(&g_cur[t*Nn + dst], 1);
  g_srcs[(size_t)t*Ee + p] = src;
}

// ---------------- GAT aggregation: fused es/ed, 8-edge batched gathers ----------------
template<int MODE>
__global__ __launch_bounds__(256) void gat_agg(const __half* __restrict__ h,
                                               const float* __restrict__ a_s,
                                               const float* __restrict__ a_d,
                                               const float* __restrict__ bias,
                                               const float* __restrict__ gam,
                                               const float* __restrict__ bet,
                                               __half* __restrict__ outh){
  int wg = blockIdx.x*8 + (threadIdx.x>>5);
  if (wg >= TN) return;
  int lane = threadIdx.x & 31;
  int t = wg / Nn;
  int d = wg - t*Nn;
  const int* off  = g_off  + t*(Nn+1);
  const int* srcs = g_srcs + (size_t)t*Ee;
  int tb = t*Nn;

  float asr[8], adr[8];
  {
    float4 a = *(const float4*)(a_s + lane*8);
    float4 b = *(const float4*)(a_s + lane*8 + 4);
    asr[0]=a.x; asr[1]=a.y; asr[2]=a.z; asr[3]=a.w;
    asr[4]=b.x; asr[5]=b.y; asr[6]=b.z; asr[7]=b.w;
    float4 c = *(const float4*)(a_d + lane*8);
    float4 e = *(const float4*)(a_d + lane*8 + 4);
    adr[0]=c.x; adr[1]=c.y; adr[2]=c.z; adr[3]=c.w;
    adr[4]=e.x; adr[5]=e.y; adr[6]=e.z; adr[7]=e.w;
  }

  float acc[8], edv=0.f;
  float s;
  {
    const int4 raw = *(const int4*)(h + (size_t)wg*Dd + lane*8);
    const __half2* hp = (const __half2*)&raw;
    float v[8], es=0.f;
#pragma unroll
    for (int q=0;q<4;q++){
      float2 f = __half22float2(hp[q]);
      v[q*2]=f.x; v[q*2+1]=f.y;
    }
#pragma unroll
    for (int c=0;c<8;c++){ edv += v[c]*adr[c]; es += v[c]*asr[c]; }
    float ev = es + edv;
    float e_self = (ev >= 0.f) ? ev : 0.2f*ev;
    float w0 = __expf(e_self);
#pragma unroll
    for (int c=0;c<8;c++) acc[c] = w0*v[c];
    s = w0;
  }

  int beg = off[d], end = off[d+1];
  int j = beg;
  // 8-edge batch: issue all 8 gathers before any math (MLP=8)
  for (; j+7 < end; j += 8){
    int4 rr[8];
#pragma unroll
    for (int u=0;u<8;u++){
      int sv = srcs[j+u];
      rr[u] = *(const int4*)(h + (size_t)(tb+sv)*Dd + lane*8);
    }
#pragma unroll
    for (int u=0;u<8;u++){
      const __half2* hp = (const __half2*)&rr[u];
      float f[8];
#pragma unroll
      for (int q=0;q<4;q++){
        float2 x = __half22float2(hp[q]);
        f[q*2]=x.x; f[q*2+1]=x.y;
      }
      float e0=edv;
#pragma unroll
      for (int c=0;c<8;c++) e0 += f[c]*asr[c];
      e0 = (e0 >= 0.f) ? e0 : 0.2f*e0;
      float w = __expf(e0);
      s += w;
#pragma unroll
      for (int c=0;c<8;c++) acc[c] += w*f[c];
    }
  }
  // 4-edge batch
  for (; j+3 < end; j += 4){
    int4 rr[4];
#pragma unroll
    for (int u=0;u<4;u++){
      int sv = srcs[j+u];
      rr[u] = *(const int4*)(h + (size_t)(tb+sv)*Dd + lane*8);
    }
#pragma unroll
    for (int u=0;u<4;u++){
      const __half2* hp = (const __half2*)&rr[u];
      float f[8];
#pragma unroll
      for (int q=0;q<4;q++){
        float2 x = __half22float2(hp[q]);
        f[q*2]=x.x; f[q*2+1]=x.y;
      }
      float e0=edv;
#pragma unroll
      for (int c=0;c<8;c++) e0 += f[c]*asr[c];
      e0 = (e0 >= 0.f) ? e0 : 0.2f*e0;
      float w = __expf(e0);
      s += w;
#pragma unroll
      for (int c=0;c<8;c++) acc[c] += w*f[c];
    }
  }
  for (; j < end; ++j){
    int sv = srcs[j];
    const int4 r0 = *(const int4*)(h + (size_t)(tb+sv)*Dd + lane*8);
    const __half2* hp = (const __half2*)&r0;
    float f[8];
#pragma unroll
    for (int q=0;q<4;q++){
      float2 x = __half22float2(hp[q]);
      f[q*2]=x.x; f[q*2+1]=x.y;
    }
    float e0=edv;
#pragma unroll
    for (int c=0;c<8;c++) e0 += f[c]*asr[c];
    e0 = (e0 >= 0.f) ? e0 : 0.2f*e0;
    float w = __expf(e0);
    s += w;
#pragma unroll
    for (int c=0;c<8;c++) acc[c] += w*f[c];
  }

  float inv = 1.f/s;
  const float* bp = bias + lane*8;
  float v[8];
#pragma unroll
  for (int c=0;c<8;c++) v[c] = acc[c]*inv + bp[c];

  if (MODE == 1){
    float sum=0.f;
#pragma unroll
    for (int c=0;c<8;c++) sum += v[c];
    sum = warp_sum(sum);
    float mu = sum*(1.f/Dd);
    float d2=0.f;
#pragma unroll
    for (int c=0;c<8;c++){ float dd=v[c]-mu; d2 += dd*dd; }
    d2 = warp_sum(d2);
    float invs = rsqrtf(d2*(1.f/Dd) + LN_EPS);
    const float* gp = gam + lane*8;
    const float* btp = bet + lane*8;
#pragma unroll
    for (int c=0;c<8;c++){
      float y = (v[c]-mu)*invs*gp[c] + btp[c];
      v[c] = fmaxf(y, 0.f);
    }
  }
  __half* op = outh + (size_t)wg*Dd + lane*8;
  __half2 o[4];
#pragma unroll
  for (int q=0;q<4;q++) o[q] = __float22half2_rn(make_float2(v[q*2], v[q*2+1]));
  *(int4*)op = *(int4*)o;
}

// ---------------- temporal attention (fp16 emb) ----------------
__global__ __launch_bounds__(256) void temporal_kernel(){
  int n = blockIdx.x*8 + (threadIdx.x>>5);
  if (n >= Nn) return;
  int lane = threadIdx.x & 31;
  float er[8][8];
#pragma unroll
  for (int s2=0;s2<8;s2++){
    const int4 raw = *(const int4*)(g_embh + ((size_t)s2*Nn + n)*Dd + lane*8);
    const __half2* hp = (const __half2*)&raw;
#pragma unroll
    for (int q=0;q<4;q++){
      float2 f = __half22float2(hp[q]);
      er[s2][q*2]=f.x; er[s2][q*2+1]=f.y;
    }
  }
  float uc[8], c1r[8];
  {
    const float* pu = g_u + (size_t)n*Dd + lane*8;
    float4 a=*(const float4*)pu, b=*(const float4*)(pu+4);
    const float* pc2 = g_c2 + lane*8;
    float4 ca=*(const float4*)pc2, cb=*(const float4*)(pc2+4);
    uc[0]=a.x+ca.x; uc[1]=a.y+ca.y; uc[2]=a.z+ca.z; uc[3]=a.w+ca.w;
    uc[4]=b.x+cb.x; uc[5]=b.y+cb.y; uc[6]=b.z+cb.z; uc[7]=b.w+cb.w;
    const float* pc1 = g_c1 + lane*8;
    float4 da=*(const float4*)pc1, db=*(const float4*)(pc1+4);
    c1r[0]=da.x; c1r[1]=da.y; c1r[2]=da.z; c1r[3]=da.w;
    c1r[4]=db.x; c1r[5]=db.y; c1r[6]=db.z; c1r[7]=db.w;
  }
  float t1p=0.f;
#pragma unroll
  for (int c=0;c<8;c++) t1p += c1r[c]*er[7][c];
  float t1 = warp_sum(t1p) + g_c0;
  float sc[8];
#pragma unroll
  for (int s2=0;s2<8;s2++){
    float p=0.f;
#pragma unroll
    for (int c=0;c<8;c++) p += uc[c]*er[s2][c];
    sc[s2] = (warp_sum(p) + t1) * 0.0625f;
  }
  float mx = sc[0];
#pragma unroll
  for (int s2=1;s2<8;s2++) mx = fmaxf(mx, sc[s2]);
  float w[8]; float den=0.f;
#pragma unroll
  for (int s2=0;s2<8;s2++){ w[s2]=__expf(sc[s2]-mx); den+=w[s2]; }
  float inv = 1.f/den;
  float xb[8];
#pragma unroll
  for (int c=0;c<8;c++){
    float a=0.f;
#pragma unroll
    for (int s2=0;s2<8;s2++) a += w[s2]*er[s2][c];
    xb[c]=a*inv;
  }
  __half* po = g_xbarh + (size_t)n*Dd + lane*8;
  __half2 o[4];
#pragma unroll
  for (int q=0;q<4;q++) o[q] = __float22half2_rn(make_float2(xb[q*2], xb[q*2+1]));
  *(int4*)po = *(int4*)o;
}

// ---------------- BatchNorm stats ----------------
__global__ void bn_part(){
  __shared__ float ss[256], sq[256];
  int col = threadIdx.x & 63;
  int rg  = threadIdx.x >> 6;
  float s=0.f, q=0.f;
  for (int n = blockIdx.x*4 + rg; n < Nn; n += 1024){
    float v = g_logits[(size_t)n*OUTC + col];
    s += v; q += v*v;
  }
  ss[threadIdx.x]=s; sq[threadIdx.x]=q;
  __syncthreads();
  if (rg==0){
    for (int r2=1;r2<4;r2++){ s += ss[r2*64+col]; q += sq[r2*64+col]; }
    g_psum[blockIdx.x*64+col]=s;
    g_psq [blockIdx.x*64+col]=q;
  }
}
__global__ void bn_final(){
  int col = threadIdx.x;
  float s=0.f, q=0.f;
  for (int b=0;b<256;b++){ s += g_psum[b*64+col]; q += g_psq[b*64+col]; }
  float mu = s/(float)Nn;
  g_mu[col]=mu;
  g_var[col]=q/(float)Nn - mu*mu;
}

// ---------------- BN apply + log_softmax ----------------
__global__ __launch_bounds__(256) void out_kernel(const float* __restrict__ bn_g,
                                                  const float* __restrict__ bn_b,
                                                  float* __restrict__ out){
  int n = blockIdx.x*8 + (threadIdx.x>>5);
  if (n >= Nn) return;
  int lane = threadIdx.x & 31;
  int c0 = lane, c1i = lane + 32;
  float y0 = (g_logits[(size_t)n*OUTC + c0]  - g_mu[c0]) * rsqrtf(g_var[c0]+LN_EPS)*bn_g[c0]+bn_b[c0];
  float y1 = (g_logits[(size_t)n*OUTC + c1i] - g_mu[c1i])* rsqrtf(g_var[c1i]+LN_EPS)*bn_g[c1i]+bn_b[c1i];
  float mx = warp_max(fmaxf(y0,y1));
  float se = warp_sum(__expf(y0-mx) + __expf(y1-mx));
  float l  = mx + logf(se);
  out[(size_t)n*OUTC + c0]  = y0 - l;
  out[(size_t)n*OUTC + c1i] = y1 - l;
}

// ---------------- orchestration ----------------
extern "C" void kernel_launch(void* const* d_in, const int* in_sizes, int n_in,
                              void* d_out, int out_size) {
  const float* feats = (const float*)d_in[0];
  const int*   ei    = (const int*)  d_in[1];
  const float* W1    = (const float*)d_in[2];
  const float* a_s1  = (const float*)d_in[3];
  const float* a_d1  = (const float*)d_in[4];
  const float* b1    = (const float*)d_in[5];
  const float* W2    = (const float*)d_in[6];
  const float* a_s2  = (const float*)d_in[7];
  const float* a_d2  = (const float*)d_in[8];
  const float* b2    = (const float*)d_in[9];
  const float* ln_g  = (const float*)d_in[10];
  const float* ln_b  = (const float*)d_in[11];
  const float* Wqkv  = (const float*)d_in[12];
  const float* bqkv  = (const float*)d_in[13];
  const float* Wo    = (const float*)d_in[14];
  const float* bo    = (const float*)d_in[15];
  const float* Wout  = (const float*)d_in[16];
  const float* bout  = (const float*)d_in[17];
  const float* bn_g  = (const float*)d_in[18];
  const float* bn_b  = (const float*)d_in[19];
  float* out = (float*)d_out;

  __half *p_h, *p_x1h, *p_embh, *p_feats16, *p_W1h, *p_W2h, *p_Mh, *p_Ph, *p_xbarh;
  float *p_bconst, *p_u, *p_logits, *p_R;
  int *p_cnt;
  cudaGetSymbolAddress((void**)&p_h,       g_h);
  cudaGetSymbolAddress((void**)&p_x1h,     g_x1h);
  cudaGetSymbolAddress((void**)&p_embh,    g_embh);
  cudaGetSymbolAddress((void**)&p_feats16, g_feats16);
  cudaGetSymbolAddress((void**)&p_W1h,     g_W1h);
  cudaGetSymbolAddress((void**)&p_W2h,     g_W2h);
  cudaGetSymbolAddress((void**)&p_Mh,      g_Mh);
  cudaGetSymbolAddress((void**)&p_Ph,      g_Ph);
  cudaGetSymbolAddress((void**)&p_bconst,  g_bconst);
  cudaGetSymbolAddress((void**)&p_u,       g_u);
  cudaGetSymbolAddress((void**)&p_xbarh,   g_xbarh);
  cudaGetSymbolAddress((void**)&p_logits,  g_logits);
  cudaGetSymbolAddress((void**)&p_R,       g_R);
  cudaGetSymbolAddress((void**)&p_cnt,     g_cnt);

  cudaFuncSetAttribute(gemm_hf<0>, cudaFuncAttributeMaxDynamicSharedMemorySize, GEMM_SMEM);
  cudaFuncSetAttribute(gemm_hf<1>, cudaFuncAttributeMaxDynamicSharedMemorySize, GEMM_SMEM);

  cudaMemsetAsync(p_cnt, 0, TN*sizeof(int));

  // converts
  f2h<<<(TN*Fin/4+255)/256,256>>>(feats, p_feats16, TN*Fin/4);
  f2h<<<(Dd*Fin/4+255)/256,256>>>(W1, p_W1h, Dd*Fin/4);
  f2h<<<(Dd*Dd/4+255)/256,256>>>(W2, p_W2h, Dd*Dd/4);

  // GAT layer 1 GEMM
  {
    dim3 grid(Dd/BN, TN/BM);
    gemm_hf<1><<<grid,256,GEMM_SMEM>>>(TN, Fin, Dd, p_feats16, p_W1h, nullptr, p_h);
  }

  // CSR for all 8 timesteps (parallel 3-phase scan)
  count_k<<<(Tt*Ee+255)/256,256>>>(ei);
  scan_p1<<<Tt*SNB,256>>>();
  scan_p2<<<1,32>>>();
  scan_p3<<<Tt*SNB,256>>>();
  scatter_k<<<(Tt*Ee+255)/256,256>>>(ei);

  gat_agg<0><<<TN/8,256>>>(p_h, a_s1, a_d1, b1, nullptr, nullptr, p_x1h);

  // GAT layer 2
  {
    dim3 grid(Dd/BN, TN/BM);
    gemm_hf<1><<<grid,256,GEMM_SMEM>>>(TN, Dd, Dd, p_x1h, p_W2h, nullptr, p_h);
  }
  gat_agg<1><<<TN/8,256>>>(p_h, a_s2, a_d2, b2, ln_g, ln_b, p_embh);

  // MHA constant folds
  foldM<<<dim3(4,4),256>>>(Wqkv);
  foldNN<0><<<dim3(4,4),256>>>(Wo, Wqkv + 2*Dd*Dd, p_R);
  foldNN<1><<<dim3(4,1),256>>>(Wout, p_R, p_Ph);
  foldVec<<<1,256>>>(Wqkv, bqkv, Wo, bo);
  foldBconst<<<1,64>>>(Wout, bout);

  // temporal attention (collapsed): u = emb7 @ M
  {
    dim3 grid(Dd/BN, (Nn+BM-1)/BM);
    gemm_hf<0><<<grid,256,GEMM_SMEM>>>(Nn, Dd, Dd, p_embh + (size_t)7*Nn*Dd, p_Mh, nullptr, p_u);
  }
  temporal_kernel<<<(Nn+7)/8,256>>>();

  // logits = xbar @ P^T + bconst
  {
    dim3 grid(1, (Nn+BM-1)/BM);
    gemm_hf<0><<<grid,256,GEMM_SMEM>>>(Nn, Dd, OUTC, p_xbarh, p_Ph, p_bconst, p_logits);
  }

  bn_part<<<256,256>>>();
  bn_final<<<1,64>>>();
  out_kernel<<<(Nn+7)/8,256>>>(bn_g, bn_b, out);
}

// round 14
// speedup vs baseline: 1.0521x; 1.0521x over previous
#include <cuda_runtime.h>
#include <cuda_fp16.h>
#include <cstdint>

#define Nn 50000
#define Ee 500000
#define Tt 8
#define Fin 128
#define Dd 256
#define Hh 32
#define OUTC 64
#define TN (Tt*Nn)
#define LN_EPS 1e-5f
#define SNB 25
#define SCHUNK 2000

// ---------------- scratch ----------------
__device__ __half g_h[(size_t)TN*Dd];
__device__ __half g_x1h[(size_t)TN*Dd];
__device__ __half g_embh[(size_t)TN*Dd];
__device__ int    g_cnt[TN];
__device__ int    g_off[Tt*(Nn+1)];
__device__ int    g_cur[TN];
__device__ int    g_bsum[Tt*SNB];
__device__ int    g_srcs[Tt*Ee];
__device__ __half g_feats16[(size_t)TN*Fin];
__device__ __half g_W1h[Dd*Fin];
__device__ __half g_W2h[Dd*Dd];
__device__ __half g_Mh[Dd*Dd];
__device__ float  g_R[Dd*Dd];
__device__ __half g_Ph[OUTC*Dd];
__device__ float  g_c1[Dd];
__device__ float  g_c2[Dd];
__device__ float  g_c0;
__device__ float  g_tvec[Dd];
__device__ float  g_bconst[OUTC];
__device__ float  g_u[(size_t)Nn*Dd];
__device__ __half g_xbarh[(size_t)Nn*Dd];
__device__ float  g_logits[(size_t)Nn*OUTC];
__device__ float  g_psum[256*OUTC];
__device__ float  g_psq[256*OUTC];
__device__ float  g_mu[OUTC];
__device__ float  g_var[OUTC];

// ---------------- helpers ----------------
__device__ __forceinline__ float warp_sum(float v){
#pragma unroll
  for (int o=16;o;o>>=1) v += __shfl_xor_sync(0xffffffffu, v, o);
  return v;
}
__device__ __forceinline__ float warp_max(float v){
#pragma unroll
  for (int o=16;o;o>>=1) v = fmaxf(v, __shfl_xor_sync(0xffffffffu, v, o));
  return v;
}
__device__ __forceinline__ void cp16(uint32_t dst, const void* src, bool p){
  int sz = p ? 16 : 0;
  asm volatile("cp.async.cg.shared.global [%0], [%1], 16, %2;"
               :: "r"(dst), "l"(src), "r"(sz) : "memory");
}

// ---------------- fp32 -> fp16 convert ----------------
__global__ void f2h(const float* __restrict__ src, __half* __restrict__ dst, int n4){
  int i = blockIdx.x*256 + threadIdx.x;
  if (i >= n4) return;
  float4 v = *(const float4*)(src + (size_t)i*4);
  __half2 a = __float22half2_rn(make_float2(v.x, v.y));
  __half2 b = __float22half2_rn(make_float2(v.z, v.w));
  *(uint2*)(dst + (size_t)i*4) = make_uint2(*(uint32_t*)&a, *(uint32_t*)&b);
}

// =====================================================================
// FP16 tensor-core GEMM (m16n8k16, fp32 accum), 128x128 tile,
// cp.async 4-stage, .cg, single sync per k-tile.  (R11 config)
// =====================================================================
#define BM 128
#define BN 128
#define BK 32
#define SASH 40
#define NSTAGE 4
#define GEMM_SMEM (NSTAGE*(BM+BN)*SASH*2)

template<int OUTH>
__global__ __launch_bounds__(256) void gemm_hf(int Mr, int K, int NC,
    const __half* __restrict__ A, const __half* __restrict__ B,
    const float* __restrict__ bias, void* __restrict__ Cv)
{
  extern __shared__ __half smem[];
  __half* Asm = smem;
  __half* Bsm = smem + NSTAGE*BM*SASH;
  const int tid = threadIdx.x;
  const int brow = blockIdx.y*BM, bcol = blockIdx.x*BN;
  const int lane = tid & 31;
  const int wid  = tid >> 5;
  const int wm = (wid & 1)*64;
  const int wn = (wid >> 1)*32;

  float acc[4][4][4];
#pragma unroll
  for (int i=0;i<4;i++)
#pragma unroll
    for (int j=0;j<4;j++)
#pragma unroll
      for (int r=0;r<4;r++) acc[i][j][r]=0.f;

  int frow[2], fcol[2];
#pragma unroll
  for (int i=0;i<2;i++){ int f = tid + i*256; frow[i]=f>>2; fcol[i]=(f&3)*8; }

  uint32_t sA = (uint32_t)__cvta_generic_to_shared(Asm);
  uint32_t sB = (uint32_t)__cvta_generic_to_shared(Bsm);

  const int lr = lane & 7, lt = lane >> 3;
  const int a_row_off = lr + ((lt & 1) ? 8 : 0);
  const int a_col_off = (lt & 2) ? 8 : 0;
  const int b_row_off = lr + ((lt & 2) ? 8 : 0);
  const int b_col_off = (lt & 1) ? 8 : 0;

  const int KT = K/BK;

  auto issue = [&](int kt, int b){
    int k0 = kt*BK;
#pragma unroll
    for (int i=0;i<2;i++){
      int gr = brow + frow[i];
      bool pa = (gr < Mr);
      const __half* srca = A + (size_t)(pa?gr:0)*K + k0 + fcol[i];
      cp16(sA + (uint32_t)(b*BM*SASH + frow[i]*SASH + fcol[i])*2u, srca, pa);
      int gc = bcol + frow[i];
      bool pb = (gc < NC);
      const __half* srcb = B + (size_t)(pb?gc:0)*K + k0 + fcol[i];
      cp16(sB + (uint32_t)(b*BN*SASH + frow[i]*SASH + fcol[i])*2u, srcb, pb);
    }
    asm volatile("cp.async.commit_group;" ::: "memory");
  };

#pragma unroll
  for (int i=0;i<NSTAGE-1;i++)
    if (i < KT) issue(i, i);

  for (int kt=0; kt<KT; ++kt){
    if (kt+3 <= KT)      asm volatile("cp.async.wait_group 2;" ::: "memory");
    else if (kt+2 <= KT) asm volatile("cp.async.wait_group 1;" ::: "memory");
    else                 asm volatile("cp.async.wait_group 0;" ::: "memory");
    __syncthreads();
    if (kt+NSTAGE-1 < KT) issue(kt+NSTAGE-1, (kt+NSTAGE-1)%NSTAGE);

    int b = kt % NSTAGE;
    uint32_t baseA = sA + (uint32_t)(b*BM*SASH)*2u;
    uint32_t baseB = sB + (uint32_t)(b*BN*SASH)*2u;
#pragma unroll
    for (int ks=0; ks<2; ++ks){
      int k = ks*16;
      uint32_t a[4][4], bb[4][2];
#pragma unroll
      for (int mi=0; mi<4; ++mi){
        uint32_t addr = baseA + (uint32_t)((wm + mi*16 + a_row_off)*SASH + k + a_col_off)*2u;
        asm volatile("ldmatrix.sync.aligned.m8n8.x4.shared.b16 {%0,%1,%2,%3}, [%4];"
          : "=r"(a[mi][0]), "=r"(a[mi][1]), "=r"(a[mi][2]), "=r"(a[mi][3]) : "r"(addr));
      }
#pragma unroll
      for (int bj=0; bj<2; ++bj){
        uint32_t addr = baseB + (uint32_t)((wn + bj*16 + b_row_off)*SASH + k + b_col_off)*2u;
        uint32_t r0,r1,r2,r3;
        asm volatile("ldmatrix.sync.aligned.m8n8.x4.shared.b16 {%0,%1,%2,%3}, [%4];"
          : "=r"(r0), "=r"(r1), "=r"(r2), "=r"(r3) : "r"(addr));
        bb[bj*2+0][0]=r0; bb[bj*2+0][1]=r1;
        bb[bj*2+1][0]=r2; bb[bj*2+1][1]=r3;
      }
#pragma unroll
      for (int mi=0; mi<4; ++mi)
#pragma unroll
        for (int nj=0; nj<4; ++nj){
          asm volatile(
            "mma.sync.aligned.m16n8k16.row.col.f32.f16.f16.f32 "
            "{%0,%1,%2,%3}, {%4,%5,%6,%7}, {%8,%9}, {%0,%1,%2,%3};"
            : "+f"(acc[mi][nj][0]), "+f"(acc[mi][nj][1]),
              "+f"(acc[mi][nj][2]), "+f"(acc[mi][nj][3])
            : "r"(a[mi][0]), "r"(a[mi][1]), "r"(a[mi][2]), "r"(a[mi][3]),
              "r"(bb[nj][0]), "r"(bb[nj][1]));
        }
    }
  }

  const int g = lane >> 2, tg = lane & 3;
#pragma unroll
  for (int mi=0; mi<4; ++mi){
    int row0 = brow + wm + mi*16 + g;
    int row1 = row0 + 8;
#pragma unroll
    for (int nj=0; nj<4; ++nj){
      int col = bcol + wn + nj*8 + tg*2;
      if (col >= NC) continue;
      if (OUTH){
        __half* C = (__half*)Cv;
        __half2 v0 = __float22half2_rn(make_float2(acc[mi][nj][0], acc[mi][nj][1]));
        __half2 v1 = __float22half2_rn(make_float2(acc[mi][nj][2], acc[mi][nj][3]));
        if (row0 < Mr) *(__half2*)(C + (size_t)row0*NC + col) = v0;
        if (row1 < Mr) *(__half2*)(C + (size_t)row1*NC + col) = v1;
      } else {
        float* C = (float*)Cv;
        float b0 = bias ? bias[col]   : 0.f;
        float b1v= bias ? bias[col+1] : 0.f;
        if (row0 < Mr) *(float2*)(C + (size_t)row0*NC + col) = make_float2(acc[mi][nj][0]+b0, acc[mi][nj][1]+b1v);
        if (row1 < Mr) *(float2*)(C + (size_t)row1*NC + col) = make_float2(acc[mi][nj][2]+b0, acc[mi][nj][3]+b1v);
      }
    }
  }
}

// ---------------- tiled small-GEMM fold kernels ----------------
__global__ __launch_bounds__(256) void foldM(const float* __restrict__ Wqkv){
  __shared__ float As[16][64];
  __shared__ float Bs[16][64];
  int tx = threadIdx.x & 15, ty = threadIdx.x >> 4;
  int bj = blockIdx.y*64, bi = blockIdx.x*64;
  float acc[4][4] = {};
  int lkk = threadIdx.x >> 4;
  int lc4 = (threadIdx.x & 15)*4;
  for (int k0=0;k0<Dd;k0+=16){
    *(float4*)&As[lkk][lc4] = *(const float4*)&Wqkv[(size_t)(Dd+k0+lkk)*Dd + bj + lc4];
    *(float4*)&Bs[lkk][lc4] = *(const float4*)&Wqkv[(size_t)(k0+lkk)*Dd + bi + lc4];
    __syncthreads();
#pragma unroll
    for (int kk=0;kk<16;kk++){
      float ar[4], br[4];
#pragma unroll
      for (int r=0;r<4;r++) ar[r]=As[kk][ty*4+r];
#pragma unroll
      for (int c=0;c<4;c++) br[c]=Bs[kk][tx*4+c];
#pragma unroll
      for (int r=0;r<4;r++)
#pragma unroll
        for (int c=0;c<4;c++) acc[r][c]+=ar[r]*br[c];
    }
    __syncthreads();
  }
#pragma unroll
  for (int r=0;r<4;r++)
#pragma unroll
    for (int c=0;c<4;c++)
      g_Mh[(size_t)(bj+ty*4+r)*Dd + bi+tx*4+c] = __float2half(acc[r][c]);
}

template<int OH>
__global__ __launch_bounds__(256) void foldNN(const float* __restrict__ A,
                                              const float* __restrict__ B,
                                              void* __restrict__ Cv){
  __shared__ float As[64][17];
  __shared__ float Bs[16][64];
  int tx = threadIdx.x & 15, ty = threadIdx.x >> 4;
  int bi = blockIdx.y*64, bj = blockIdx.x*64;
  float acc[4][4] = {};
  int arow = threadIdx.x >> 2;
  int akc  = (threadIdx.x & 3)*4;
  int bkk  = threadIdx.x >> 4;
  int bc4  = (threadIdx.x & 15)*4;
  for (int k0=0;k0<Dd;k0+=16){
    float4 av = *(const float4*)&A[(size_t)(bi+arow)*Dd + k0 + akc];
    As[arow][akc+0]=av.x; As[arow][akc+1]=av.y; As[arow][akc+2]=av.z; As[arow][akc+3]=av.w;
    *(float4*)&Bs[bkk][bc4] = *(const float4*)&B[(size_t)(k0+bkk)*Dd + bj + bc4];
    __syncthreads();
#pragma unroll
    for (int kk=0;kk<16;kk++){
      float ar[4], br[4];
#pragma unroll
      for (int r=0;r<4;r++) ar[r]=As[ty*4+r][kk];
#pragma unroll
      for (int c=0;c<4;c++) br[c]=Bs[kk][tx*4+c];
#pragma unroll
      for (int r=0;r<4;r++)
#pragma unroll
        for (int c=0;c<4;c++) acc[r][c]+=ar[r]*br[c];
    }
    __syncthreads();
  }
#pragma unroll
  for (int r=0;r<4;r++)
#pragma unroll
    for (int c=0;c<4;c++){
      if (OH) ((__half*)Cv)[(size_t)(bi+ty*4+r)*Dd + bj+tx*4+c] = __float2half(acc[r][c]);
      else    ((float*)Cv)[(size_t)(bi+ty*4+r)*Dd + bj+tx*4+c] = acc[r][c];
    }
}

__global__ void foldVec(const float* __restrict__ Wqkv, const float* __restrict__ bqkv,
                        const float* __restrict__ Wo, const float* __restrict__ bo){
  int i = threadIdx.x;
  float s1=0.f, s2=0.f, tv=0.f;
  for (int k=0;k<Dd;k++){
    s1 += Wqkv[k*Dd+i]*bqkv[Dd+k];
    s2 += Wqkv[(Dd+k)*Dd+i]*bqkv[k];
    tv += Wo[i*Dd+k]*bqkv[2*Dd+k];
  }
  g_c1[i]=s1; g_c2[i]=s2; g_tvec[i]=tv+bo[i];
  if (i==0){
    float s0=0.f;
    for (int k=0;k<Dd;k++) s0 += bqkv[k]*bqkv[Dd+k];
    g_c0=s0;
  }
}
__global__ void foldBconst(const float* __restrict__ Wout, const float* __restrict__ bout){
  int o = threadIdx.x;
  if (o < OUTC){
    float b=0.f;
    for (int k=0;k<Dd;k++) b += Wout[o*Dd+k]*g_tvec[k];
    g_bconst[o]=b+bout[o];
  }
}

// ---------------- CSR build ----------------
__global__ void count_k(const int* __restrict__ ei){
  int idx = blockIdx.x*256 + threadIdx.x;
  if (idx >= Tt*Ee) return;
  int t = idx / Ee, e = idx - t*Ee;
  int dst = ei[(size_t)t*2*Ee + Ee + e];
  atomicAdd(&g_cnt[t*Nn + dst], 1);
}
__global__ void scan_p1(){
  int bid = blockIdx.x;
  int t = bid/SNB, b = bid - t*SNB;
  const int* cnt = g_cnt + t*Nn + b*SCHUNK;
  __shared__ int sh[256];
  int tid = threadIdx.x;
  int s = 0;
  if (tid < 250){
#pragma unroll
    for (int i=0;i<8;i++) s += cnt[tid*8+i];
  }
  sh[tid]=s; __syncthreads();
  for (int d=128; d; d>>=1){ if (tid<d) sh[tid]+=sh[tid+d]; __syncthreads(); }
  if (tid==0) g_bsum[bid]=sh[0];
}
__global__ void scan_p2(){
  int t = threadIdx.x;
  if (t < Tt){
    int run=0;
    for (int b=0;b<SNB;b++){
      int v = g_bsum[t*SNB+b];
      g_bsum[t*SNB+b] = run;
      run += v;
    }
    g_off[t*(Nn+1)+Nn] = run;
  }
}
__global__ void scan_p3(){
  int bid = blockIdx.x;
  int t = bid/SNB, b = bid - t*SNB;
  int base = t*Nn + b*SCHUNK;
  const int* cnt = g_cnt + base;
  int* off = g_off + t*(Nn+1) + b*SCHUNK;
  int* cur = g_cur + base;
  __shared__ int sh[256];
  int tid = threadIdx.x;
  int vals[8]; int s=0;
  if (tid < 250){
#pragma unroll
    for (int i=0;i<8;i++){ vals[i]=cnt[tid*8+i]; s+=vals[i]; }
  }
  sh[tid]=s; __syncthreads();
  for (int d=1; d<256; d<<=1){
    int v = (tid>=d)? sh[tid-d]:0;
    __syncthreads();
    sh[tid]+=v;
    __syncthreads();
  }
  int run = g_bsum[bid] + ((tid==0)?0:sh[tid-1]);
  if (tid < 250){
#pragma unroll
    for (int i=0;i<8;i++){
      off[tid*8+i]=run; cur[tid*8+i]=run; run += vals[i];
    }
  }
}
__global__ void scatter_k(const int* __restrict__ ei){
  int idx = blockIdx.x*256 + threadIdx.x;
  if (idx >= Tt*Ee) return;
  int t = idx / Ee, e = idx - t*Ee;
  int src = ei[(size_t)t*2*Ee + e];
  int dst = ei[(size_t)t*2*Ee + Ee + e];
  int p = atomicAdd(&g_cur[t*Nn + dst], 1);
  g_srcs[(size_t)t*Ee + p] = src;
}

// ---------------- GAT aggregation: fused es/ed, 4-edge unroll (R11) ----------------
template<int MODE>
__global__ __launch_bounds__(256) void gat_agg(const __half* __restrict__ h,
                                               const float* __restrict__ a_s,
                                               const float* __restrict__ a_d,
                                               const float* __restrict__ bias,
                                               const float* __restrict__ gam,
                                               const float* __restrict__ bet,
                                               __half* __restrict__ outh){
  int wg = blockIdx.x*8 + (threadIdx.x>>5);
  if (wg >= TN) return;
  int lane = threadIdx.x & 31;
  int t = wg / Nn;
  int d = wg - t*Nn;
  const int* off  = g_off  + t*(Nn+1);
  const int* srcs = g_srcs + (size_t)t*Ee;
  int tb = t*Nn;

  float asr[8], adr[8];
  {
    float4 a = *(const float4*)(a_s + lane*8);
    float4 b = *(const float4*)(a_s + lane*8 + 4);
    asr[0]=a.x; asr[1]=a.y; asr[2]=a.z; asr[3]=a.w;
    asr[4]=b.x; asr[5]=b.y; asr[6]=b.z; asr[7]=b.w;
    float4 c = *(const float4*)(a_d + lane*8);
    float4 e = *(const float4*)(a_d + lane*8 + 4);
    adr[0]=c.x; adr[1]=c.y; adr[2]=c.z; adr[3]=c.w;
    adr[4]=e.x; adr[5]=e.y; adr[6]=e.z; adr[7]=e.w;
  }

  float acc[8], edv=0.f;
  float s;
  {
    const int4 raw = *(const int4*)(h + (size_t)wg*Dd + lane*8);
    const __half2* hp = (const __half2*)&raw;
    float v[8], es=0.f;
#pragma unroll
    for (int q=0;q<4;q++){
      float2 f = __half22float2(hp[q]);
      v[q*2]=f.x; v[q*2+1]=f.y;
    }
#pragma unroll
    for (int c=0;c<8;c++){ edv += v[c]*adr[c]; es += v[c]*asr[c]; }
    float ev = es + edv;
    float e_self = (ev >= 0.f) ? ev : 0.2f*ev;
    float w0 = __expf(e_self);
#pragma unroll
    for (int c=0;c<8;c++) acc[c] = w0*v[c];
    s = w0;
  }

  int beg = off[d], end = off[d+1];
  int j = beg;
  for (; j+3 < end; j += 4){
    int s0 = srcs[j],   s1 = srcs[j+1];
    int s2v = srcs[j+2], s3 = srcs[j+3];
    const int4 r0 = *(const int4*)(h + (size_t)(tb+s0)*Dd + lane*8);
    const int4 r1 = *(const int4*)(h + (size_t)(tb+s1)*Dd + lane*8);
    const int4 r2 = *(const int4*)(h + (size_t)(tb+s2v)*Dd + lane*8);
    const int4 r3 = *(const int4*)(h + (size_t)(tb+s3)*Dd + lane*8);
    const __half2* h0 = (const __half2*)&r0;
    const __half2* h1 = (const __half2*)&r1;
    const __half2* h2 = (const __half2*)&r2;
    const __half2* h3 = (const __half2*)&r3;
    float fa[8], fb[8], fc[8], fd[8];
#pragma unroll
    for (int q=0;q<4;q++){
      float2 x0 = __half22float2(h0[q]);
      float2 x1 = __half22float2(h1[q]);
      float2 x2 = __half22float2(h2[q]);
      float2 x3 = __half22float2(h3[q]);
      fa[q*2]=x0.x; fa[q*2+1]=x0.y;
      fb[q*2]=x1.x; fb[q*2+1]=x1.y;
      fc[q*2]=x2.x; fc[q*2+1]=x2.y;
      fd[q*2]=x3.x; fd[q*2+1]=x3.y;
    }
    float e0=edv, e1=edv, e2=edv, e3=edv;
#pragma unroll
    for (int c=0;c<8;c++){
      e0 += fa[c]*asr[c]; e1 += fb[c]*asr[c];
      e2 += fc[c]*asr[c]; e3 += fd[c]*asr[c];
    }
    e0 = (e0 >= 0.f) ? e0 : 0.2f*e0;
    e1 = (e1 >= 0.f) ? e1 : 0.2f*e1;
    e2 = (e2 >= 0.f) ? e2 : 0.2f*e2;
    e3 = (e3 >= 0.f) ? e3 : 0.2f*e3;
    float wA = __expf(e0), wB = __expf(e1), wC = __expf(e2), wD = __expf(e3);
    s += (wA + wB) + (wC + wD);
#pragma unroll
    for (int c=0;c<8;c++) acc[c] += (wA*fa[c] + wB*fb[c]) + (wC*fc[c] + wD*fd[c]);
  }
  for (; j < end; ++j){
    int s0 = srcs[j];
    const int4 r0 = *(const int4*)(h + (size_t)(tb+s0)*Dd + lane*8);
    const __half2* h0 = (const __half2*)&r0;
    float fa[8];
#pragma unroll
    for (int q=0;q<4;q++){
      float2 x = __half22float2(h0[q]);
      fa[q*2]=x.x; fa[q*2+1]=x.y;
    }
    float e0=edv;
#pragma unroll
    for (int c=0;c<8;c++) e0 += fa[c]*asr[c];
    e0 = (e0 >= 0.f) ? e0 : 0.2f*e0;
    float wA = __expf(e0);
    s += wA;
#pragma unroll
    for (int c=0;c<8;c++) acc[c] += wA*fa[c];
  }

  float inv = 1.f/s;
  const float* bp = bias + lane*8;
  float v[8];
#pragma unroll
  for (int c=0;c<8;c++) v[c] = acc[c]*inv + bp[c];

  if (MODE == 1){
    float sum=0.f;
#pragma unroll
    for (int c=0;c<8;c++) sum += v[c];
    sum = warp_sum(sum);
    float mu = sum*(1.f/Dd);
    float d2=0.f;
#pragma unroll
    for (int c=0;c<8;c++){ float dd=v[c]-mu; d2 += dd*dd; }
    d2 = warp_sum(d2);
    float invs = rsqrtf(d2*(1.f/Dd) + LN_EPS);
    const float* gp = gam + lane*8;
    const float* btp = bet + lane*8;
#pragma unroll
    for (int c=0;c<8;c++){
      float y = (v[c]-mu)*invs*gp[c] + btp[c];
      v[c] = fmaxf(y, 0.f);
    }
  }
  __half* op = outh + (size_t)wg*Dd + lane*8;
  __half2 o[4];
#pragma unroll
  for (int q=0;q<4;q++) o[q] = __float22half2_rn(make_float2(v[q*2], v[q*2+1]));
  *(int4*)op = *(int4*)o;
}

// ---------------- temporal attention (fp16 emb) ----------------
__global__ __launch_bounds__(256) void temporal_kernel(){
  int n = blockIdx.x*8 + (threadIdx.x>>5);
  if (n >= Nn) return;
  int lane = threadIdx.x & 31;
  float er[8][8];
#pragma unroll
  for (int s2=0;s2<8;s2++){
    const int4 raw = *(const int4*)(g_embh + ((size_t)s2*Nn + n)*Dd + lane*8);
    const __half2* hp = (const __half2*)&raw;
#pragma unroll
    for (int q=0;q<4;q++){
      float2 f = __half22float2(hp[q]);
      er[s2][q*2]=f.x; er[s2][q*2+1]=f.y;
    }
  }
  float uc[8], c1r[8];
  {
    const float* pu = g_u + (size_t)n*Dd + lane*8;
    float4 a=*(const float4*)pu, b=*(const float4*)(pu+4);
    const float* pc2 = g_c2 + lane*8;
    float4 ca=*(const float4*)pc2, cb=*(const float4*)(pc2+4);
    uc[0]=a.x+ca.x; uc[1]=a.y+ca.y; uc[2]=a.z+ca.z; uc[3]=a.w+ca.w;
    uc[4]=b.x+cb.x; uc[5]=b.y+cb.y; uc[6]=b.z+cb.z; uc[7]=b.w+cb.w;
    const float* pc1 = g_c1 + lane*8;
    float4 da=*(const float4*)pc1, db=*(const float4*)(pc1+4);
    c1r[0]=da.x; c1r[1]=da.y; c1r[2]=da.z; c1r[3]=da.w;
    c1r[4]=db.x; c1r[5]=db.y; c1r[6]=db.z; c1r[7]=db.w;
  }
  float t1p=0.f;
#pragma unroll
  for (int c=0;c<8;c++) t1p += c1r[c]*er[7][c];
  float t1 = warp_sum(t1p) + g_c0;
  float sc[8];
#pragma unroll
  for (int s2=0;s2<8;s2++){
    float p=0.f;
#pragma unroll
    for (int c=0;c<8;c++) p += uc[c]*er[s2][c];
    sc[s2] = (warp_sum(p) + t1) * 0.0625f;
  }
  float mx = sc[0];
#pragma unroll
  for (int s2=1;s2<8;s2++) mx = fmaxf(mx, sc[s2]);
  float w[8]; float den=0.f;
#pragma unroll
  for (int s2=0;s2<8;s2++){ w[s2]=__expf(sc[s2]-mx); den+=w[s2]; }
  float inv = 1.f/den;
  float xb[8];
#pragma unroll
  for (int c=0;c<8;c++){
    float a=0.f;
#pragma unroll
    for (int s2=0;s2<8;s2++) a += w[s2]*er[s2][c];
    xb[c]=a*inv;
  }
  __half* po = g_xbarh + (size_t)n*Dd + lane*8;
  __half2 o[4];
#pragma unroll
  for (int q=0;q<4;q++) o[q] = __float22half2_rn(make_float2(xb[q*2], xb[q*2+1]));
  *(int4*)po = *(int4*)o;
}

// ---------------- BatchNorm stats ----------------
__global__ void bn_part(){
  __shared__ float ss[256], sq[256];
  int col = threadIdx.x & 63;
  int rg  = threadIdx.x >> 6;
  float s=0.f, q=0.f;
  for (int n = blockIdx.x*4 + rg; n < Nn; n += 1024){
    float v = g_logits[(size_t)n*OUTC + col];
    s += v; q += v*v;
  }
  ss[threadIdx.x]=s; sq[threadIdx.x]=q;
  __syncthreads();
  if (rg==0){
    for (int r2=1;r2<4;r2++){ s += ss[r2*64+col]; q += sq[r2*64+col]; }
    g_psum[blockIdx.x*64+col]=s;
    g_psq [blockIdx.x*64+col]=q;
  }
}
__global__ void bn_final(){
  int col = threadIdx.x;
  float s=0.f, q=0.f;
  for (int b=0;b<256;b++){ s += g_psum[b*64+col]; q += g_psq[b*64+col]; }
  float mu = s/(float)Nn;
  g_mu[col]=mu;
  g_var[col]=q/(float)Nn - mu*mu;
}

// ---------------- BN apply + log_softmax ----------------
__global__ __launch_bounds__(256) void out_kernel(const float* __restrict__ bn_g,
                                                  const float* __restrict__ bn_b,
                                                  float* __restrict__ out){
  int n = blockIdx.x*8 + (threadIdx.x>>5);
  if (n >= Nn) return;
  int lane = threadIdx.x & 31;
  int c0 = lane, c1i = lane + 32;
  float y0 = (g_logits[(size_t)n*OUTC + c0]  - g_mu[c0]) * rsqrtf(g_var[c0]+LN_EPS)*bn_g[c0]+bn_b[c0];
  float y1 = (g_logits[(size_t)n*OUTC + c1i] - g_mu[c1i])* rsqrtf(g_var[c1i]+LN_EPS)*bn_g[c1i]+bn_b[c1i];
  float mx = warp_max(fmaxf(y0,y1));
  float se = warp_sum(__expf(y0-mx) + __expf(y1-mx));
  float l  = mx + logf(se);
  out[(size_t)n*OUTC + c0]  = y0 - l;
  out[(size_t)n*OUTC + c1i] = y1 - l;
}

// ---------------- orchestration ----------------
extern "C" void kernel_launch(void* const* d_in, const int* in_sizes, int n_in,
                              void* d_out, int out_size) {
  const float* feats = (const float*)d_in[0];
  const int*   ei    = (const int*)  d_in[1];
  const float* W1    = (const float*)d_in[2];
  const float* a_s1  = (const float*)d_in[3];
  const float* a_d1  = (const float*)d_in[4];
  const float* b1    = (const float*)d_in[5];
  const float* W2    = (const float*)d_in[6];
  const float* a_s2  = (const float*)d_in[7];
  const float* a_d2  = (const float*)d_in[8];
  const float* b2    = (const float*)d_in[9];
  const float* ln_g  = (const float*)d_in[10];
  const float* ln_b  = (const float*)d_in[11];
  const float* Wqkv  = (const float*)d_in[12];
  const float* bqkv  = (const float*)d_in[13];
  const float* Wo    = (const float*)d_in[14];
  const float* bo    = (const float*)d_in[15];
  const float* Wout  = (const float*)d_in[16];
  const float* bout  = (const float*)d_in[17];
  const float* bn_g  = (const float*)d_in[18];
  const float* bn_b  = (const float*)d_in[19];
  float* out = (float*)d_out;

  __half *p_h, *p_x1h, *p_embh, *p_feats16, *p_W1h, *p_W2h, *p_Mh, *p_Ph, *p_xbarh;
  float *p_bconst, *p_u, *p_logits, *p_R;
  int *p_cnt;
  cudaGetSymbolAddress((void**)&p_h,       g_h);
  cudaGetSymbolAddress((void**)&p_x1h,     g_x1h);
  cudaGetSymbolAddress((void**)&p_embh,    g_embh);
  cudaGetSymbolAddress((void**)&p_feats16, g_feats16);
  cudaGetSymbolAddress((void**)&p_W1h,     g_W1h);
  cudaGetSymbolAddress((void**)&p_W2h,     g_W2h);
  cudaGetSymbolAddress((void**)&p_Mh,      g_Mh);
  cudaGetSymbolAddress((void**)&p_Ph,      g_Ph);
  cudaGetSymbolAddress((void**)&p_bconst,  g_bconst);
  cudaGetSymbolAddress((void**)&p_u,       g_u);
  cudaGetSymbolAddress((void**)&p_xbarh,   g_xbarh);
  cudaGetSymbolAddress((void**)&p_logits,  g_logits);
  cudaGetSymbolAddress((void**)&p_R,       g_R);
  cudaGetSymbolAddress((void**)&p_cnt,     g_cnt);

  cudaFuncSetAttribute(gemm_hf<0>, cudaFuncAttributeMaxDynamicSharedMemorySize, GEMM_SMEM);
  cudaFuncSetAttribute(gemm_hf<1>, cudaFuncAttributeMaxDynamicSharedMemorySize, GEMM_SMEM);

  cudaMemsetAsync(p_cnt, 0, TN*sizeof(int));

  // converts
  f2h<<<(TN*Fin/4+255)/256,256>>>(feats, p_feats16, TN*Fin/4);
  f2h<<<(Dd*Fin/4+255)/256,256>>>(W1, p_W1h, Dd*Fin/4);
  f2h<<<(Dd*Dd/4+255)/256,256>>>(W2, p_W2h, Dd*Dd/4);

  // GAT layer 1 GEMM
  {
    dim3 grid(Dd/BN, TN/BM);
    gemm_hf<1><<<grid,256,GEMM_SMEM>>>(TN, Fin, Dd, p_feats16, p_W1h, nullptr, p_h);
  }

  // CSR for all 8 timesteps (parallel 3-phase scan)
  count_k<<<(Tt*Ee+255)/256,256>>>(ei);
  scan_p1<<<Tt*SNB,256>>>();
  scan_p2<<<1,32>>>();
  scan_p3<<<Tt*SNB,256>>>();
  scatter_k<<<(Tt*Ee+255)/256,256>>>(ei);

  gat_agg<0><<<TN/8,256>>>(p_h, a_s1, a_d1, b1, nullptr, nullptr, p_x1h);

  // GAT layer 2
  {
    dim3 grid(Dd/BN, TN/BM);
    gemm_hf<1><<<grid,256,GEMM_SMEM>>>(TN, Dd, Dd, p_x1h, p_W2h, nullptr, p_h);
  }
  gat_agg<1><<<TN/8,256>>>(p_h, a_s2, a_d2, b2, ln_g, ln_b, p_embh);

  // MHA constant folds
  foldM<<<dim3(4,4),256>>>(Wqkv);
  foldNN<0><<<dim3(4,4),256>>>(Wo, Wqkv + 2*Dd*Dd, p_R);
  foldNN<1><<<dim3(4,1),256>>>(Wout, p_R, p_Ph);
  foldVec<<<1,256>>>(Wqkv, bqkv, Wo, bo);
  foldBconst<<<1,64>>>(Wout, bout);

  // temporal attention (collapsed): u = emb7 @ M
  {
    dim3 grid(Dd/BN, (Nn+BM-1)/BM);
    gemm_hf<0><<<grid,256,GEMM_SMEM>>>(Nn, Dd, Dd, p_embh + (size_t)7*Nn*Dd, p_Mh, nullptr, p_u);
  }
  temporal_kernel<<<(Nn+7)/8,256>>>();

  // logits = xbar @ P^T + bconst
  {
    dim3 grid(1, (Nn+BM-1)/BM);
    gemm_hf<0><<<grid,256,GEMM_SMEM>>>(Nn, Dd, OUTC, p_xbarh, p_Ph, p_bconst, p_logits);
  }

  bn_part<<<256,256>>>();
  bn_final<<<1,64>>>();
  out_kernel<<<(Nn+7)/8,256>>>(bn_g, bn_b, out);
}

// round 15
// speedup vs baseline: 1.0666x; 1.0139x over previous
#include <cuda_runtime.h>
#include <cuda_fp16.h>
#include <cstdint>

#define Nn 50000
#define Ee 500000
#define Tt 8
#define Fin 128
#define Dd 256
#define Hh 32
#define OUTC 64
#define TN (Tt*Nn)
#define LN_EPS 1e-5f
#define SNB 25
#define SCHUNK 2000

// ---------------- scratch ----------------
__device__ __half g_h[(size_t)TN*Dd];
__device__ __half g_x1h[(size_t)TN*Dd];
__device__ __half g_embh[(size_t)TN*Dd];
__device__ int    g_cnt[TN];
__device__ int    g_off[Tt*(Nn+1)];
__device__ int    g_cur[TN];
__device__ int    g_bsum[Tt*SNB];
__device__ int    g_srcs[Tt*Ee];
__device__ __half g_feats16[(size_t)TN*Fin];
__device__ __half g_W1h[Dd*Fin];
__device__ __half g_W2h[Dd*Dd];
__device__ __half g_Mh[Dd*Dd];
__device__ float  g_R[Dd*Dd];
__device__ __half g_Ph[OUTC*Dd];
__device__ float  g_c1[Dd];
__device__ float  g_c2[Dd];
__device__ float  g_c0;
__device__ float  g_tvec[Dd];
__device__ float  g_bconst[OUTC];
__device__ float  g_u[(size_t)Nn*Dd];
__device__ __half g_xbarh[(size_t)Nn*Dd];
__device__ float  g_logits[(size_t)Nn*OUTC];
__device__ float  g_psum[256*OUTC];
__device__ float  g_psq[256*OUTC];
__device__ float  g_mu[OUTC];
__device__ float  g_var[OUTC];

// ---------------- helpers ----------------
__device__ __forceinline__ float warp_sum(float v){
#pragma unroll
  for (int o=16;o;o>>=1) v += __shfl_xor_sync(0xffffffffu, v, o);
  return v;
}
__device__ __forceinline__ float warp_max(float v){
#pragma unroll
  for (int o=16;o;o>>=1) v = fmaxf(v, __shfl_xor_sync(0xffffffffu, v, o));
  return v;
}
__device__ __forceinline__ void cp16(uint32_t dst, const void* src, bool p){
  int sz = p ? 16 : 0;
  asm volatile("cp.async.cg.shared.global [%0], [%1], 16, %2;"
               :: "r"(dst), "l"(src), "r"(sz) : "memory");
}

// ---------------- fp32 -> fp16 convert ----------------
__global__ void f2h(const float* __restrict__ src, __half* __restrict__ dst, int n4){
  int i = blockIdx.x*256 + threadIdx.x;
  if (i >= n4) return;
  float4 v = *(const float4*)(src + (size_t)i*4);
  __half2 a = __float22half2_rn(make_float2(v.x, v.y));
  __half2 b = __float22half2_rn(make_float2(v.z, v.w));
  *(uint2*)(dst + (size_t)i*4) = make_uint2(*(uint32_t*)&a, *(uint32_t*)&b);
}

// =====================================================================
// FP16 tensor-core GEMM (m16n8k16, fp32 accum), 128x128 tile,
// cp.async 4-stage, .cg, single sync per k-tile.  (R11 config)
// =====================================================================
#define BM 128
#define BN 128
#define BK 32
#define SASH 40
#define NSTAGE 4
#define GEMM_SMEM (NSTAGE*(BM+BN)*SASH*2)

template<int OUTH>
__global__ __launch_bounds__(256) void gemm_hf(int Mr, int K, int NC,
    const __half* __restrict__ A, const __half* __restrict__ B,
    const float* __restrict__ bias, void* __restrict__ Cv)
{
  extern __shared__ __half smem[];
  __half* Asm = smem;
  __half* Bsm = smem + NSTAGE*BM*SASH;
  const int tid = threadIdx.x;
  const int brow = blockIdx.y*BM, bcol = blockIdx.x*BN;
  const int lane = tid & 31;
  const int wid  = tid >> 5;
  const int wm = (wid & 1)*64;
  const int wn = (wid >> 1)*32;

  float acc[4][4][4];
#pragma unroll
  for (int i=0;i<4;i++)
#pragma unroll
    for (int j=0;j<4;j++)
#pragma unroll
      for (int r=0;r<4;r++) acc[i][j][r]=0.f;

  int frow[2], fcol[2];
#pragma unroll
  for (int i=0;i<2;i++){ int f = tid + i*256; frow[i]=f>>2; fcol[i]=(f&3)*8; }

  uint32_t sA = (uint32_t)__cvta_generic_to_shared(Asm);
  uint32_t sB = (uint32_t)__cvta_generic_to_shared(Bsm);

  const int lr = lane & 7, lt = lane >> 3;
  const int a_row_off = lr + ((lt & 1) ? 8 : 0);
  const int a_col_off = (lt & 2) ? 8 : 0;
  const int b_row_off = lr + ((lt & 2) ? 8 : 0);
  const int b_col_off = (lt & 1) ? 8 : 0;

  const int KT = K/BK;

  auto issue = [&](int kt, int b){
    int k0 = kt*BK;
#pragma unroll
    for (int i=0;i<2;i++){
      int gr = brow + frow[i];
      bool pa = (gr < Mr);
      const __half* srca = A + (size_t)(pa?gr:0)*K + k0 + fcol[i];
      cp16(sA + (uint32_t)(b*BM*SASH + frow[i]*SASH + fcol[i])*2u, srca, pa);
      int gc = bcol + frow[i];
      bool pb = (gc < NC);
      const __half* srcb = B + (size_t)(pb?gc:0)*K + k0 + fcol[i];
      cp16(sB + (uint32_t)(b*BN*SASH + frow[i]*SASH + fcol[i])*2u, srcb, pb);
    }
    asm volatile("cp.async.commit_group;" ::: "memory");
  };

#pragma unroll
  for (int i=0;i<NSTAGE-1;i++)
    if (i < KT) issue(i, i);

  for (int kt=0; kt<KT; ++kt){
    if (kt+3 <= KT)      asm volatile("cp.async.wait_group 2;" ::: "memory");
    else if (kt+2 <= KT) asm volatile("cp.async.wait_group 1;" ::: "memory");
    else                 asm volatile("cp.async.wait_group 0;" ::: "memory");
    __syncthreads();
    if (kt+NSTAGE-1 < KT) issue(kt+NSTAGE-1, (kt+NSTAGE-1)%NSTAGE);

    int b = kt % NSTAGE;
    uint32_t baseA = sA + (uint32_t)(b*BM*SASH)*2u;
    uint32_t baseB = sB + (uint32_t)(b*BN*SASH)*2u;
#pragma unroll
    for (int ks=0; ks<2; ++ks){
      int k = ks*16;
      uint32_t a[4][4], bb[4][2];
#pragma unroll
      for (int mi=0; mi<4; ++mi){
        uint32_t addr = baseA + (uint32_t)((wm + mi*16 + a_row_off)*SASH + k + a_col_off)*2u;
        asm volatile("ldmatrix.sync.aligned.m8n8.x4.shared.b16 {%0,%1,%2,%3}, [%4];"
          : "=r"(a[mi][0]), "=r"(a[mi][1]), "=r"(a[mi][2]), "=r"(a[mi][3]) : "r"(addr));
      }
#pragma unroll
      for (int bj=0; bj<2; ++bj){
        uint32_t addr = baseB + (uint32_t)((wn + bj*16 + b_row_off)*SASH + k + b_col_off)*2u;
        uint32_t r0,r1,r2,r3;
        asm volatile("ldmatrix.sync.aligned.m8n8.x4.shared.b16 {%0,%1,%2,%3}, [%4];"
          : "=r"(r0), "=r"(r1), "=r"(r2), "=r"(r3) : "r"(addr));
        bb[bj*2+0][0]=r0; bb[bj*2+0][1]=r1;
        bb[bj*2+1][0]=r2; bb[bj*2+1][1]=r3;
      }
#pragma unroll
      for (int mi=0; mi<4; ++mi)
#pragma unroll
        for (int nj=0; nj<4; ++nj){
          asm volatile(
            "mma.sync.aligned.m16n8k16.row.col.f32.f16.f16.f32 "
            "{%0,%1,%2,%3}, {%4,%5,%6,%7}, {%8,%9}, {%0,%1,%2,%3};"
            : "+f"(acc[mi][nj][0]), "+f"(acc[mi][nj][1]),
              "+f"(acc[mi][nj][2]), "+f"(acc[mi][nj][3])
            : "r"(a[mi][0]), "r"(a[mi][1]), "r"(a[mi][2]), "r"(a[mi][3]),
              "r"(bb[nj][0]), "r"(bb[nj][1]));
        }
    }
  }

  const int g = lane >> 2, tg = lane & 3;
#pragma unroll
  for (int mi=0; mi<4; ++mi){
    int row0 = brow + wm + mi*16 + g;
    int row1 = row0 + 8;
#pragma unroll
    for (int nj=0; nj<4; ++nj){
      int col = bcol + wn + nj*8 + tg*2;
      if (col >= NC) continue;
      if (OUTH){
        __half* C = (__half*)Cv;
        __half2 v0 = __float22half2_rn(make_float2(acc[mi][nj][0], acc[mi][nj][1]));
        __half2 v1 = __float22half2_rn(make_float2(acc[mi][nj][2], acc[mi][nj][3]));
        if (row0 < Mr) *(__half2*)(C + (size_t)row0*NC + col) = v0;
        if (row1 < Mr) *(__half2*)(C + (size_t)row1*NC + col) = v1;
      } else {
        float* C = (float*)Cv;
        float b0 = bias ? bias[col]   : 0.f;
        float b1v= bias ? bias[col+1] : 0.f;
        if (row0 < Mr) *(float2*)(C + (size_t)row0*NC + col) = make_float2(acc[mi][nj][0]+b0, acc[mi][nj][1]+b1v);
        if (row1 < Mr) *(float2*)(C + (size_t)row1*NC + col) = make_float2(acc[mi][nj][2]+b0, acc[mi][nj][3]+b1v);
      }
    }
  }
}

// ---------------- tiled small-GEMM fold kernels ----------------
__global__ __launch_bounds__(256) void foldM(const float* __restrict__ Wqkv){
  __shared__ float As[16][64];
  __shared__ float Bs[16][64];
  int tx = threadIdx.x & 15, ty = threadIdx.x >> 4;
  int bj = blockIdx.y*64, bi = blockIdx.x*64;
  float acc[4][4] = {};
  int lkk = threadIdx.x >> 4;
  int lc4 = (threadIdx.x & 15)*4;
  for (int k0=0;k0<Dd;k0+=16){
    *(float4*)&As[lkk][lc4] = *(const float4*)&Wqkv[(size_t)(Dd+k0+lkk)*Dd + bj + lc4];
    *(float4*)&Bs[lkk][lc4] = *(const float4*)&Wqkv[(size_t)(k0+lkk)*Dd + bi + lc4];
    __syncthreads();
#pragma unroll
    for (int kk=0;kk<16;kk++){
      float ar[4], br[4];
#pragma unroll
      for (int r=0;r<4;r++) ar[r]=As[kk][ty*4+r];
#pragma unroll
      for (int c=0;c<4;c++) br[c]=Bs[kk][tx*4+c];
#pragma unroll
      for (int r=0;r<4;r++)
#pragma unroll
        for (int c=0;c<4;c++) acc[r][c]+=ar[r]*br[c];
    }
    __syncthreads();
  }
#pragma unroll
  for (int r=0;r<4;r++)
#pragma unroll
    for (int c=0;c<4;c++)
      g_Mh[(size_t)(bj+ty*4+r)*Dd + bi+tx*4+c] = __float2half(acc[r][c]);
}

template<int OH>
__global__ __launch_bounds__(256) void foldNN(const float* __restrict__ A,
                                              const float* __restrict__ B,
                                              void* __restrict__ Cv){
  __shared__ float As[64][17];
  __shared__ float Bs[16][64];
  int tx = threadIdx.x & 15, ty = threadIdx.x >> 4;
  int bi = blockIdx.y*64, bj = blockIdx.x*64;
  float acc[4][4] = {};
  int arow = threadIdx.x >> 2;
  int akc  = (threadIdx.x & 3)*4;
  int bkk  = threadIdx.x >> 4;
  int bc4  = (threadIdx.x & 15)*4;
  for (int k0=0;k0<Dd;k0+=16){
    float4 av = *(const float4*)&A[(size_t)(bi+arow)*Dd + k0 + akc];
    As[arow][akc+0]=av.x; As[arow][akc+1]=av.y; As[arow][akc+2]=av.z; As[arow][akc+3]=av.w;
    *(float4*)&Bs[bkk][bc4] = *(const float4*)&B[(size_t)(k0+bkk)*Dd + bj + bc4];
    __syncthreads();
#pragma unroll
    for (int kk=0;kk<16;kk++){
      float ar[4], br[4];
#pragma unroll
      for (int r=0;r<4;r++) ar[r]=As[ty*4+r][kk];
#pragma unroll
      for (int c=0;c<4;c++) br[c]=Bs[kk][tx*4+c];
#pragma unroll
      for (int r=0;r<4;r++)
#pragma unroll
        for (int c=0;c<4;c++) acc[r][c]+=ar[r]*br[c];
    }
    __syncthreads();
  }
#pragma unroll
  for (int r=0;r<4;r++)
#pragma unroll
    for (int c=0;c<4;c++){
      if (OH) ((__half*)Cv)[(size_t)(bi+ty*4+r)*Dd + bj+tx*4+c] = __float2half(acc[r][c]);
      else    ((float*)Cv)[(size_t)(bi+ty*4+r)*Dd + bj+tx*4+c] = acc[r][c];
    }
}

__global__ void foldVec(const float* __restrict__ Wqkv, const float* __restrict__ bqkv,
                        const float* __restrict__ Wo, const float* __restrict__ bo){
  int i = threadIdx.x;
  float s1=0.f, s2=0.f, tv=0.f;
  for (int k=0;k<Dd;k++){
    s1 += Wqkv[k*Dd+i]*bqkv[Dd+k];
    s2 += Wqkv[(Dd+k)*Dd+i]*bqkv[k];
    tv += Wo[i*Dd+k]*bqkv[2*Dd+k];
  }
  g_c1[i]=s1; g_c2[i]=s2; g_tvec[i]=tv+bo[i];
  if (i==0){
    float s0=0.f;
    for (int k=0;k<Dd;k++) s0 += bqkv[k]*bqkv[Dd+k];
    g_c0=s0;
  }
}
__global__ void foldBconst(const float* __restrict__ Wout, const float* __restrict__ bout){
  int o = threadIdx.x;
  if (o < OUTC){
    float b=0.f;
    for (int k=0;k<Dd;k++) b += Wout[o*Dd+k]*g_tvec[k];
    g_bconst[o]=b+bout[o];
  }
}

// ---------------- CSR build ----------------
__global__ void count_k(const int* __restrict__ ei){
  int idx = blockIdx.x*256 + threadIdx.x;
  if (idx >= Tt*Ee) return;
  int t = idx / Ee, e = idx - t*Ee;
  int dst = ei[(size_t)t*2*Ee + Ee + e];
  atomicAdd(&g_cnt[t*Nn + dst], 1);
}
__global__ void scan_p1(){
  int bid = blockIdx.x;
  int t = bid/SNB, b = bid - t*SNB;
  const int* cnt = g_cnt + t*Nn + b*SCHUNK;
  __shared__ int sh[256];
  int tid = threadIdx.x;
  int s = 0;
  if (tid < 250){
#pragma unroll
    for (int i=0;i<8;i++) s += cnt[tid*8+i];
  }
  sh[tid]=s; __syncthreads();
  for (int d=128; d; d>>=1){ if (tid<d) sh[tid]+=sh[tid+d]; __syncthreads(); }
  if (tid==0) g_bsum[bid]=sh[0];
}
__global__ void scan_p2(){
  int t = threadIdx.x;
  if (t < Tt){
    int run=0;
    for (int b=0;b<SNB;b++){
      int v = g_bsum[t*SNB+b];
      g_bsum[t*SNB+b] = run;
      run += v;
    }
    g_off[t*(Nn+1)+Nn] = run;
  }
}
__global__ void scan_p3(){
  int bid = blockIdx.x;
  int t = bid/SNB, b = bid - t*SNB;
  int base = t*Nn + b*SCHUNK;
  const int* cnt = g_cnt + base;
  int* off = g_off + t*(Nn+1) + b*SCHUNK;
  int* cur = g_cur + base;
  __shared__ int sh[256];
  int tid = threadIdx.x;
  int vals[8]; int s=0;
  if (tid < 250){
#pragma unroll
    for (int i=0;i<8;i++){ vals[i]=cnt[tid*8+i]; s+=vals[i]; }
  }
  sh[tid]=s; __syncthreads();
  for (int d=1; d<256; d<<=1){
    int v = (tid>=d)? sh[tid-d]:0;
    __syncthreads();
    sh[tid]+=v;
    __syncthreads();
  }
  int run = g_bsum[bid] + ((tid==0)?0:sh[tid-1]);
  if (tid < 250){
#pragma unroll
    for (int i=0;i<8;i++){
      off[tid*8+i]=run; cur[tid*8+i]=run; run += vals[i];
    }
  }
}
__global__ void scatter_k(const int* __restrict__ ei){
  int idx = blockIdx.x*256 + threadIdx.x;
  if (idx >= Tt*Ee) return;
  int t = idx / Ee, e = idx - t*Ee;
  int src = ei[(size_t)t*2*Ee + e];
  int dst = ei[(size_t)t*2*Ee + Ee + e];
  int p = atomicAdd(&g_cur[t*Nn + dst], 1);
  g_srcs[(size_t)t*Ee + p] = src;
}

// ---------------- GAT aggregation: fused es/ed, half2 math, dual accumulators ----------------
template<int MODE>
__global__ __launch_bounds__(256) void gat_agg(const __half* __restrict__ h,
                                               const float* __restrict__ a_s,
                                               const float* __restrict__ a_d,
                                               const float* __restrict__ bias,
                                               const float* __restrict__ gam,
                                               const float* __restrict__ bet,
                                               __half* __restrict__ outh){
  int wg = blockIdx.x*8 + (threadIdx.x>>5);
  if (wg >= TN) return;
  int lane = threadIdx.x & 31;
  int t = wg / Nn;
  int d = wg - t*Nn;
  const int* off  = g_off  + t*(Nn+1);
  const int* srcs = g_srcs + (size_t)t*Ee;
  int tb = t*Nn;

  // per-lane attention vectors (head = lane), fp32 + half2 copies
  float asr[8], adr[8];
  __half2 as2[4];
  {
    float4 a = *(const float4*)(a_s + lane*8);
    float4 b = *(const float4*)(a_s + lane*8 + 4);
    asr[0]=a.x; asr[1]=a.y; asr[2]=a.z; asr[3]=a.w;
    asr[4]=b.x; asr[5]=b.y; asr[6]=b.z; asr[7]=b.w;
    float4 c = *(const float4*)(a_d + lane*8);
    float4 e = *(const float4*)(a_d + lane*8 + 4);
    adr[0]=c.x; adr[1]=c.y; adr[2]=c.z; adr[3]=c.w;
    adr[4]=e.x; adr[5]=e.y; adr[6]=e.z; adr[7]=e.w;
#pragma unroll
    for (int q=0;q<4;q++)
      as2[q] = __floats2half2_rn(asr[q*2], asr[q*2+1]);
  }

  // own row: edv + self-edge (fp32), init acc (half2)
  __half2 accA[4], accB[4];
  float edv=0.f, s;
  {
    const int4 raw = *(const int4*)(h + (size_t)wg*Dd + lane*8);
    const __half2* hp = (const __half2*)&raw;
    float v[8], es=0.f;
#pragma unroll
    for (int q=0;q<4;q++){
      float2 f = __half22float2(hp[q]);
      v[q*2]=f.x; v[q*2+1]=f.y;
    }
#pragma unroll
    for (int c=0;c<8;c++){ edv += v[c]*adr[c]; es += v[c]*asr[c]; }
    float ev = es + edv;
    float e_self = (ev >= 0.f) ? ev : 0.2f*ev;
    float w0 = __expf(e_self);
    __half2 w0h = __half2half2(__float2half_rn(w0));
#pragma unroll
    for (int q=0;q<4;q++){
      accA[q] = __hmul2(w0h, hp[q]);
      accB[q] = __floats2half2_rn(0.f, 0.f);
    }
    s = w0;
  }

  int beg = off[d], end = off[d+1];
  int j = beg;
  for (; j+3 < end; j += 4){
    int s0 = srcs[j],   s1 = srcs[j+1];
    int s2v = srcs[j+2], s3 = srcs[j+3];
    const int4 r0 = *(const int4*)(h + (size_t)(tb+s0)*Dd + lane*8);
    const int4 r1 = *(const int4*)(h + (size_t)(tb+s1)*Dd + lane*8);
    const int4 r2 = *(const int4*)(h + (size_t)(tb+s2v)*Dd + lane*8);
    const int4 r3 = *(const int4*)(h + (size_t)(tb+s3)*Dd + lane*8);
    const __half2* h0 = (const __half2*)&r0;
    const __half2* h1 = (const __half2*)&r1;
    const __half2* h2 = (const __half2*)&r2;
    const __half2* h3 = (const __half2*)&r3;
    // half2 dot products
    __half2 d0 = __hmul2(h0[0], as2[0]);
    __half2 d1 = __hmul2(h1[0], as2[0]);
    __half2 d2 = __hmul2(h2[0], as2[0]);
    __half2 d3 = __hmul2(h3[0], as2[0]);
#pragma unroll
    for (int q=1;q<4;q++){
      d0 = __hfma2(h0[q], as2[q], d0);
      d1 = __hfma2(h1[q], as2[q], d1);
      d2 = __hfma2(h2[q], as2[q], d2);
      d3 = __hfma2(h3[q], as2[q], d3);
    }
    float e0 = edv + __low2float(d0) + __high2float(d0);
    float e1 = edv + __low2float(d1) + __high2float(d1);
    float e2 = edv + __low2float(d2) + __high2float(d2);
    float e3 = edv + __low2float(d3) + __high2float(d3);
    e0 = (e0 >= 0.f) ? e0 : 0.2f*e0;
    e1 = (e1 >= 0.f) ? e1 : 0.2f*e1;
    e2 = (e2 >= 0.f) ? e2 : 0.2f*e2;
    e3 = (e3 >= 0.f) ? e3 : 0.2f*e3;
    float wA = __expf(e0), wB = __expf(e1), wC = __expf(e2), wD = __expf(e3);
    s += (wA + wB) + (wC + wD);
    __half2 whA = __half2half2(__float2half_rn(wA));
    __half2 whB = __half2half2(__float2half_rn(wB));
    __half2 whC = __half2half2(__float2half_rn(wC));
    __half2 whD = __half2half2(__float2half_rn(wD));
#pragma unroll
    for (int q=0;q<4;q++){
      accA[q] = __hfma2(whA, h0[q], accA[q]);
      accB[q] = __hfma2(whB, h1[q], accB[q]);
      accA[q] = __hfma2(whC, h2[q], accA[q]);
      accB[q] = __hfma2(whD, h3[q], accB[q]);
    }
  }
  for (; j < end; ++j){
    int s0 = srcs[j];
    const int4 r0 = *(const int4*)(h + (size_t)(tb+s0)*Dd + lane*8);
    const __half2* h0 = (const __half2*)&r0;
    __half2 d0 = __hmul2(h0[0], as2[0]);
#pragma unroll
    for (int q=1;q<4;q++) d0 = __hfma2(h0[q], as2[q], d0);
    float e0 = edv + __low2float(d0) + __high2float(d0);
    e0 = (e0 >= 0.f) ? e0 : 0.2f*e0;
    float wA = __expf(e0);
    s += wA;
    __half2 whA = __half2half2(__float2half_rn(wA));
#pragma unroll
    for (int q=0;q<4;q++) accA[q] = __hfma2(whA, h0[q], accA[q]);
  }

  float inv = 1.f/s;
  const float* bp = bias + lane*8;
  float v[8];
#pragma unroll
  for (int q=0;q<4;q++){
    float2 a = __half22float2(accA[q]);
    float2 b = __half22float2(accB[q]);
    v[q*2]   = (a.x + b.x)*inv + bp[q*2];
    v[q*2+1] = (a.y + b.y)*inv + bp[q*2+1];
  }

  if (MODE == 1){
    float sum=0.f;
#pragma unroll
    for (int c=0;c<8;c++) sum += v[c];
    sum = warp_sum(sum);
    float mu = sum*(1.f/Dd);
    float d2s=0.f;
#pragma unroll
    for (int c=0;c<8;c++){ float dd=v[c]-mu; d2s += dd*dd; }
    d2s = warp_sum(d2s);
    float invs = rsqrtf(d2s*(1.f/Dd) + LN_EPS);
    const float* gp = gam + lane*8;
    const float* btp = bet + lane*8;
#pragma unroll
    for (int c=0;c<8;c++){
      float y = (v[c]-mu)*invs*gp[c] + btp[c];
      v[c] = fmaxf(y, 0.f);
    }
  }
  __half* op = outh + (size_t)wg*Dd + lane*8;
  __half2 o[4];
#pragma unroll
  for (int q=0;q<4;q++) o[q] = __float22half2_rn(make_float2(v[q*2], v[q*2+1]));
  *(int4*)op = *(int4*)o;
}

// ---------------- temporal attention (fp16 emb) ----------------
__global__ __launch_bounds__(256) void temporal_kernel(){
  int n = blockIdx.x*8 + (threadIdx.x>>5);
  if (n >= Nn) return;
  int lane = threadIdx.x & 31;
  float er[8][8];
#pragma unroll
  for (int s2=0;s2<8;s2++){
    const int4 raw = *(const int4*)(g_embh + ((size_t)s2*Nn + n)*Dd + lane*8);
    const __half2* hp = (const __half2*)&raw;
#pragma unroll
    for (int q=0;q<4;q++){
      float2 f = __half22float2(hp[q]);
      er[s2][q*2]=f.x; er[s2][q*2+1]=f.y;
    }
  }
  float uc[8], c1r[8];
  {
    const float* pu = g_u + (size_t)n*Dd + lane*8;
    float4 a=*(const float4*)pu, b=*(const float4*)(pu+4);
    const float* pc2 = g_c2 + lane*8;
    float4 ca=*(const float4*)pc2, cb=*(const float4*)(pc2+4);
    uc[0]=a.x+ca.x; uc[1]=a.y+ca.y; uc[2]=a.z+ca.z; uc[3]=a.w+ca.w;
    uc[4]=b.x+cb.x; uc[5]=b.y+cb.y; uc[6]=b.z+cb.z; uc[7]=b.w+cb.w;
    const float* pc1 = g_c1 + lane*8;
    float4 da=*(const float4*)pc1, db=*(const float4*)(pc1+4);
    c1r[0]=da.x; c1r[1]=da.y; c1r[2]=da.z; c1r[3]=da.w;
    c1r[4]=db.x; c1r[5]=db.y; c1r[6]=db.z; c1r[7]=db.w;
  }
  float t1p=0.f;
#pragma unroll
  for (int c=0;c<8;c++) t1p += c1r[c]*er[7][c];
  float t1 = warp_sum(t1p) + g_c0;
  float sc[8];
#pragma unroll
  for (int s2=0;s2<8;s2++){
    float p=0.f;
#pragma unroll
    for (int c=0;c<8;c++) p += uc[c]*er[s2][c];
    sc[s2] = (warp_sum(p) + t1) * 0.0625f;
  }
  float mx = sc[0];
#pragma unroll
  for (int s2=1;s2<8;s2++) mx = fmaxf(mx, sc[s2]);
  float w[8]; float den=0.f;
#pragma unroll
  for (int s2=0;s2<8;s2++){ w[s2]=__expf(sc[s2]-mx); den+=w[s2]; }
  float inv = 1.f/den;
  float xb[8];
#pragma unroll
  for (int c=0;c<8;c++){
    float a=0.f;
#pragma unroll
    for (int s2=0;s2<8;s2++) a += w[s2]*er[s2][c];
    xb[c]=a*inv;
  }
  __half* po = g_xbarh + (size_t)n*Dd + lane*8;
  __half2 o[4];
#pragma unroll
  for (int q=0;q<4;q++) o[q] = __float22half2_rn(make_float2(xb[q*2], xb[q*2+1]));
  *(int4*)po = *(int4*)o;
}

// ---------------- BatchNorm stats ----------------
__global__ void bn_part(){
  __shared__ float ss[256], sq[256];
  int col = threadIdx.x & 63;
  int rg  = threadIdx.x >> 6;
  float s=0.f, q=0.f;
  for (int n = blockIdx.x*4 + rg; n < Nn; n += 1024){
    float v = g_logits[(size_t)n*OUTC + col];
    s += v; q += v*v;
  }
  ss[threadIdx.x]=s; sq[threadIdx.x]=q;
  __syncthreads();
  if (rg==0){
    for (int r2=1;r2<4;r2++){ s += ss[r2*64+col]; q += sq[r2*64+col]; }
    g_psum[blockIdx.x*64+col]=s;
    g_psq [blockIdx.x*64+col]=q;
  }
}
__global__ void bn_final(){
  int col = threadIdx.x;
  float s=0.f, q=0.f;
  for (int b=0;b<256;b++){ s += g_psum[b*64+col]; q += g_psq[b*64+col]; }
  float mu = s/(float)Nn;
  g_mu[col]=mu;
  g_var[col]=q/(float)Nn - mu*mu;
}

// ---------------- BN apply + log_softmax ----------------
__global__ __launch_bounds__(256) void out_kernel(const float* __restrict__ bn_g,
                                                  const float* __restrict__ bn_b,
                                                  float* __restrict__ out){
  int n = blockIdx.x*8 + (threadIdx.x>>5);
  if (n >= Nn) return;
  int lane = threadIdx.x & 31;
  int c0 = lane, c1i = lane + 32;
  float y0 = (g_logits[(size_t)n*OUTC + c0]  - g_mu[c0]) * rsqrtf(g_var[c0]+LN_EPS)*bn_g[c0]+bn_b[c0];
  float y1 = (g_logits[(size_t)n*OUTC + c1i] - g_mu[c1i])* rsqrtf(g_var[c1i]+LN_EPS)*bn_g[c1i]+bn_b[c1i];
  float mx = warp_max(fmaxf(y0,y1));
  float se = warp_sum(__expf(y0-mx) + __expf(y1-mx));
  float l  = mx + logf(se);
  out[(size_t)n*OUTC + c0]  = y0 - l;
  out[(size_t)n*OUTC + c1i] = y1 - l;
}

// ---------------- orchestration ----------------
extern "C" void kernel_launch(void* const* d_in, const int* in_sizes, int n_in,
                              void* d_out, int out_size) {
  const float* feats = (const float*)d_in[0];
  const int*   ei    = (const int*)  d_in[1];
  const float* W1    = (const float*)d_in[2];
  const float* a_s1  = (const float*)d_in[3];
  const float* a_d1  = (const float*)d_in[4];
  const float* b1    = (const float*)d_in[5];
  const float* W2    = (const float*)d_in[6];
  const float* a_s2  = (const float*)d_in[7];
  const float* a_d2  = (const float*)d_in[8];
  const float* b2    = (const float*)d_in[9];
  const float* ln_g  = (const float*)d_in[10];
  const float* ln_b  = (const float*)d_in[11];
  const float* Wqkv  = (const float*)d_in[12];
  const float* bqkv  = (const float*)d_in[13];
  const float* Wo    = (const float*)d_in[14];
  const float* bo    = (const float*)d_in[15];
  const float* Wout  = (const float*)d_in[16];
  const float* bout  = (const float*)d_in[17];
  const float* bn_g  = (const float*)d_in[18];
  const float* bn_b  = (const float*)d_in[19];
  float* out = (float*)d_out;

  __half *p_h, *p_x1h, *p_embh, *p_feats16, *p_W1h, *p_W2h, *p_Mh, *p_Ph, *p_xbarh;
  float *p_bconst, *p_u, *p_logits, *p_R;
  int *p_cnt;
  cudaGetSymbolAddress((void**)&p_h,       g_h);
  cudaGetSymbolAddress((void**)&p_x1h,     g_x1h);
  cudaGetSymbolAddress((void**)&p_embh,    g_embh);
  cudaGetSymbolAddress((void**)&p_feats16, g_feats16);
  cudaGetSymbolAddress((void**)&p_W1h,     g_W1h);
  cudaGetSymbolAddress((void**)&p_W2h,     g_W2h);
  cudaGetSymbolAddress((void**)&p_Mh,      g_Mh);
  cudaGetSymbolAddress((void**)&p_Ph,      g_Ph);
  cudaGetSymbolAddress((void**)&p_bconst,  g_bconst);
  cudaGetSymbolAddress((void**)&p_u,       g_u);
  cudaGetSymbolAddress((void**)&p_xbarh,   g_xbarh);
  cudaGetSymbolAddress((void**)&p_logits,  g_logits);
  cudaGetSymbolAddress((void**)&p_R,       g_R);
  cudaGetSymbolAddress((void**)&p_cnt,     g_cnt);

  cudaFuncSetAttribute(gemm_hf<0>, cudaFuncAttributeMaxDynamicSharedMemorySize, GEMM_SMEM);
  cudaFuncSetAttribute(gemm_hf<1>, cudaFuncAttributeMaxDynamicSharedMemorySize, GEMM_SMEM);

  cudaMemsetAsync(p_cnt, 0, TN*sizeof(int));

  // converts
  f2h<<<(TN*Fin/4+255)/256,256>>>(feats, p_feats16, TN*Fin/4);
  f2h<<<(Dd*Fin/4+255)/256,256>>>(W1, p_W1h, Dd*Fin/4);
  f2h<<<(Dd*Dd/4+255)/256,256>>>(W2, p_W2h, Dd*Dd/4);

  // GAT layer 1 GEMM
  {
    dim3 grid(Dd/BN, TN/BM);
    gemm_hf<1><<<grid,256,GEMM_SMEM>>>(TN, Fin, Dd, p_feats16, p_W1h, nullptr, p_h);
  }

  // CSR for all 8 timesteps (parallel 3-phase scan)
  count_k<<<(Tt*Ee+255)/256,256>>>(ei);
  scan_p1<<<Tt*SNB,256>>>();
  scan_p2<<<1,32>>>();
  scan_p3<<<Tt*SNB,256>>>();
  scatter_k<<<(Tt*Ee+255)/256,256>>>(ei);

  gat_agg<0><<<TN/8,256>>>(p_h, a_s1, a_d1, b1, nullptr, nullptr, p_x1h);

  // GAT layer 2
  {
    dim3 grid(Dd/BN, TN/BM);
    gemm_hf<1><<<grid,256,GEMM_SMEM>>>(TN, Dd, Dd, p_x1h, p_W2h, nullptr, p_h);
  }
  gat_agg<1><<<TN/8,256>>>(p_h, a_s2, a_d2, b2, ln_g, ln_b, p_embh);

  // MHA constant folds
  foldM<<<dim3(4,4),256>>>(Wqkv);
  foldNN<0><<<dim3(4,4),256>>>(Wo, Wqkv + 2*Dd*Dd, p_R);
  foldNN<1><<<dim3(4,1),256>>>(Wout, p_R, p_Ph);
  foldVec<<<1,256>>>(Wqkv, bqkv, Wo, bo);
  foldBconst<<<1,64>>>(Wout, bout);

  // temporal attention (collapsed): u = emb7 @ M
  {
    dim3 grid(Dd/BN, (Nn+BM-1)/BM);
    gemm_hf<0><<<grid,256,GEMM_SMEM>>>(Nn, Dd, Dd, p_embh + (size_t)7*Nn*Dd, p_Mh, nullptr, p_u);
  }
  temporal_kernel<<<(Nn+7)/8,256>>>();

  // logits = xbar @ P^T + bconst
  {
    dim3 grid(1, (Nn+BM-1)/BM);
    gemm_hf<0><<<grid,256,GEMM_SMEM>>>(Nn, Dd, OUTC, p_xbarh, p_Ph, p_bconst, p_logits);
  }

  bn_part<<<256,256>>>();
  bn_final<<<1,64>>>();
  out_kernel<<<(Nn+7)/8,256>>>(bn_g, bn_b, out);
}

// round 17
// speedup vs baseline: 1.0893x; 1.0213x over previous
#include <cuda_runtime.h>
#include <cuda_fp16.h>
#include <cstdint>

#define Nn 50000
#define Ee 500000
#define Tt 8
#define Fin 128
#define Dd 256
#define Hh 32
#define OUTC 64
#define TN (Tt*Nn)
#define LN_EPS 1e-5f
#define SNB 25
#define SCHUNK 2000

// ---------------- scratch ----------------
__device__ __half g_h[(size_t)TN*Dd];
__device__ __half g_x1h[(size_t)TN*Dd];
__device__ __half g_embh[(size_t)TN*Dd];
__device__ int    g_cnt[TN];
__device__ int    g_off[Tt*(Nn+1)];
__device__ int    g_cur[TN];
__device__ int    g_bsum[Tt*SNB];
__device__ int    g_srcs[Tt*Ee];
__device__ __half g_feats16[(size_t)TN*Fin];
__device__ __half g_W1h[Dd*Fin];
__device__ __half g_W2h[Dd*Dd];
__device__ __half g_Mh[Dd*Dd];
__device__ float  g_R[Dd*Dd];
__device__ __half g_Ph[OUTC*Dd];
__device__ float  g_c1[Dd];
__device__ float  g_c2[Dd];
__device__ float  g_c0;
__device__ float  g_tvec[Dd];
__device__ float  g_bconst[OUTC];
__device__ float  g_u[(size_t)Nn*Dd];
__device__ __half g_xbarh[(size_t)Nn*Dd];
__device__ float  g_logits[(size_t)Nn*OUTC];
__device__ float  g_psum[256*OUTC];
__device__ float  g_psq[256*OUTC];
__device__ float  g_mu[OUTC];
__device__ float  g_var[OUTC];

// ---------------- helpers ----------------
__device__ __forceinline__ float warp_sum(float v){
#pragma unroll
  for (int o=16;o;o>>=1) v += __shfl_xor_sync(0xffffffffu, v, o);
  return v;
}
__device__ __forceinline__ float warp_max(float v){
#pragma unroll
  for (int o=16;o;o>>=1) v = fmaxf(v, __shfl_xor_sync(0xffffffffu, v, o));
  return v;
}
__device__ __forceinline__ void cp16(uint32_t dst, const void* src, bool p){
  int sz = p ? 16 : 0;
  asm volatile("cp.async.cg.shared.global [%0], [%1], 16, %2;"
               :: "r"(dst), "l"(src), "r"(sz) : "memory");
}

// ---------------- fp32 -> fp16 convert ----------------
__global__ void f2h(const float* __restrict__ src, __half* __restrict__ dst, int n4){
  int i = blockIdx.x*256 + threadIdx.x;
  if (i >= n4) return;
  float4 v = *(const float4*)(src + (size_t)i*4);
  __half2 a = __float22half2_rn(make_float2(v.x, v.y));
  __half2 b = __float22half2_rn(make_float2(v.z, v.w));
  *(uint2*)(dst + (size_t)i*4) = make_uint2(*(uint32_t*)&a, *(uint32_t*)&b);
}

// =====================================================================
// FP16 mma.sync GEMM: 128x128 tile, cp.async 4-stage.  (R11/R15 config)
// =====================================================================
#define BM 128
#define BN 128
#define BK 32
#define SASH 40
#define NSTAGE 4
#define GEMM_SMEM (NSTAGE*(BM+BN)*SASH*2)

template<int OUTH>
__global__ __launch_bounds__(256) void gemm_hf(int Mr, int K, int NC,
    const __half* __restrict__ A, const __half* __restrict__ B,
    const float* __restrict__ bias, void* __restrict__ Cv)
{
  extern __shared__ __half smem[];
  __half* Asm = smem;
  __half* Bsm = smem + NSTAGE*BM*SASH;
  const int tid = threadIdx.x;
  const int brow = blockIdx.y*BM, bcol = blockIdx.x*BN;
  const int lane = tid & 31;
  const int wid  = tid >> 5;
  const int wm = (wid & 1)*64;
  const int wn = (wid >> 1)*32;

  float acc[4][4][4];
#pragma unroll
  for (int i=0;i<4;i++)
#pragma unroll
    for (int j=0;j<4;j++)
#pragma unroll
      for (int r=0;r<4;r++) acc[i][j][r]=0.f;

  int frow[2], fcol[2];
#pragma unroll
  for (int i=0;i<2;i++){ int f = tid + i*256; frow[i]=f>>2; fcol[i]=(f&3)*8; }

  uint32_t sA = (uint32_t)__cvta_generic_to_shared(Asm);
  uint32_t sB = (uint32_t)__cvta_generic_to_shared(Bsm);

  const int lr = lane & 7, lt = lane >> 3;
  const int a_row_off = lr + ((lt & 1) ? 8 : 0);
  const int a_col_off = (lt & 2) ? 8 : 0;
  const int b_row_off = lr + ((lt & 2) ? 8 : 0);
  const int b_col_off = (lt & 1) ? 8 : 0;

  const int KT = K/BK;

  auto issue = [&](int kt, int b){
    int k0 = kt*BK;
#pragma unroll
    for (int i=0;i<2;i++){
      int gr = brow + frow[i];
      bool pa = (gr < Mr);
      const __half* srca = A + (size_t)(pa?gr:0)*K + k0 + fcol[i];
      cp16(sA + (uint32_t)(b*BM*SASH + frow[i]*SASH + fcol[i])*2u, srca, pa);
      int gc = bcol + frow[i];
      bool pb = (gc < NC);
      const __half* srcb = B + (size_t)(pb?gc:0)*K + k0 + fcol[i];
      cp16(sB + (uint32_t)(b*BN*SASH + frow[i]*SASH + fcol[i])*2u, srcb, pb);
    }
    asm volatile("cp.async.commit_group;" ::: "memory");
  };

#pragma unroll
  for (int i=0;i<NSTAGE-1;i++)
    if (i < KT) issue(i, i);

  for (int kt=0; kt<KT; ++kt){
    if (kt+3 <= KT)      asm volatile("cp.async.wait_group 2;" ::: "memory");
    else if (kt+2 <= KT) asm volatile("cp.async.wait_group 1;" ::: "memory");
    else                 asm volatile("cp.async.wait_group 0;" ::: "memory");
    __syncthreads();
    if (kt+NSTAGE-1 < KT) issue(kt+NSTAGE-1, (kt+NSTAGE-1)%NSTAGE);

    int b = kt % NSTAGE;
    uint32_t baseA = sA + (uint32_t)(b*BM*SASH)*2u;
    uint32_t baseB = sB + (uint32_t)(b*BN*SASH)*2u;
#pragma unroll
    for (int ks=0; ks<2; ++ks){
      int k = ks*16;
      uint32_t a[4][4], bb[4][2];
#pragma unroll
      for (int mi=0; mi<4; ++mi){
        uint32_t addr = baseA + (uint32_t)((wm + mi*16 + a_row_off)*SASH + k + a_col_off)*2u;
        asm volatile("ldmatrix.sync.aligned.m8n8.x4.shared.b16 {%0,%1,%2,%3}, [%4];"
          : "=r"(a[mi][0]), "=r"(a[mi][1]), "=r"(a[mi][2]), "=r"(a[mi][3]) : "r"(addr));
      }
#pragma unroll
      for (int bj=0; bj<2; ++bj){
        uint32_t addr = baseB + (uint32_t)((wn + bj*16 + b_row_off)*SASH + k + b_col_off)*2u;
        uint32_t r0,r1,r2,r3;
        asm volatile("ldmatrix.sync.aligned.m8n8.x4.shared.b16 {%0,%1,%2,%3}, [%4];"
          : "=r"(r0), "=r"(r1), "=r"(r2), "=r"(r3) : "r"(addr));
        bb[bj*2+0][0]=r0; bb[bj*2+0][1]=r1;
        bb[bj*2+1][0]=r2; bb[bj*2+1][1]=r3;
      }
#pragma unroll
      for (int mi=0; mi<4; ++mi)
#pragma unroll
        for (int nj=0; nj<4; ++nj){
          asm volatile(
            "mma.sync.aligned.m16n8k16.row.col.f32.f16.f16.f32 "
            "{%0,%1,%2,%3}, {%4,%5,%6,%7}, {%8,%9}, {%0,%1,%2,%3};"
            : "+f"(acc[mi][nj][0]), "+f"(acc[mi][nj][1]),
              "+f"(acc[mi][nj][2]), "+f"(acc[mi][nj][3])
            : "r"(a[mi][0]), "r"(a[mi][1]), "r"(a[mi][2]), "r"(a[mi][3]),
              "r"(bb[nj][0]), "r"(bb[nj][1]));
        }
    }
  }

  const int g = lane >> 2, tg = lane & 3;
#pragma unroll
  for (int mi=0; mi<4; ++mi){
    int row0 = brow + wm + mi*16 + g;
    int row1 = row0 + 8;
#pragma unroll
    for (int nj=0; nj<4; ++nj){
      int col = bcol + wn + nj*8 + tg*2;
      if (col >= NC) continue;
      if (OUTH){
        __half* C = (__half*)Cv;
        __half2 v0 = __float22half2_rn(make_float2(acc[mi][nj][0], acc[mi][nj][1]));
        __half2 v1 = __float22half2_rn(make_float2(acc[mi][nj][2], acc[mi][nj][3]));
        if (row0 < Mr) *(__half2*)(C + (size_t)row0*NC + col) = v0;
        if (row1 < Mr) *(__half2*)(C + (size_t)row1*NC + col) = v1;
      } else {
        float* C = (float*)Cv;
        float b0 = bias ? bias[col]   : 0.f;
        float b1v= bias ? bias[col+1] : 0.f;
        if (row0 < Mr) *(float2*)(C + (size_t)row0*NC + col) = make_float2(acc[mi][nj][0]+b0, acc[mi][nj][1]+b1v);
        if (row1 < Mr) *(float2*)(C + (size_t)row1*NC + col) = make_float2(acc[mi][nj][2]+b0, acc[mi][nj][3]+b1v);
      }
    }
  }
}

// ---------------- tiled small-GEMM fold kernels ----------------
__global__ __launch_bounds__(256) void foldM(const float* __restrict__ Wqkv){
  __shared__ float As[16][64];
  __shared__ float Bs[16][64];
  int tx = threadIdx.x & 15, ty = threadIdx.x >> 4;
  int bj = blockIdx.y*64, bi = blockIdx.x*64;
  float acc[4][4] = {};
  int lkk = threadIdx.x >> 4;
  int lc4 = (threadIdx.x & 15)*4;
  for (int k0=0;k0<Dd;k0+=16){
    *(float4*)&As[lkk][lc4] = *(const float4*)&Wqkv[(size_t)(Dd+k0+lkk)*Dd + bj + lc4];
    *(float4*)&Bs[lkk][lc4] = *(const float4*)&Wqkv[(size_t)(k0+lkk)*Dd + bi + lc4];
    __syncthreads();
#pragma unroll
    for (int kk=0;kk<16;kk++){
      float ar[4], br[4];
#pragma unroll
      for (int r=0;r<4;r++) ar[r]=As[kk][ty*4+r];
#pragma unroll
      for (int c=0;c<4;c++) br[c]=Bs[kk][tx*4+c];
#pragma unroll
      for (int r=0;r<4;r++)
#pragma unroll
        for (int c=0;c<4;c++) acc[r][c]+=ar[r]*br[c];
    }
    __syncthreads();
  }
#pragma unroll
  for (int r=0;r<4;r++)
#pragma unroll
    for (int c=0;c<4;c++)
      g_Mh[(size_t)(bj+ty*4+r)*Dd + bi+tx*4+c] = __float2half(acc[r][c]);
}

template<int OH>
__global__ __launch_bounds__(256) void foldNN(const float* __restrict__ A,
                                              const float* __restrict__ B,
                                              void* __restrict__ Cv){
  __shared__ float As[64][17];
  __shared__ float Bs[16][64];
  int tx = threadIdx.x & 15, ty = threadIdx.x >> 4;
  int bi = blockIdx.y*64, bj = blockIdx.x*64;
  float acc[4][4] = {};
  int arow = threadIdx.x >> 2;
  int akc  = (threadIdx.x & 3)*4;
  int bkk  = threadIdx.x >> 4;
  int bc4  = (threadIdx.x & 15)*4;
  for (int k0=0;k0<Dd;k0+=16){
    float4 av = *(const float4*)&A[(size_t)(bi+arow)*Dd + k0 + akc];
    As[arow][akc+0]=av.x; As[arow][akc+1]=av.y; As[arow][akc+2]=av.z; As[arow][akc+3]=av.w;
    *(float4*)&Bs[bkk][bc4] = *(const float4*)&B[(size_t)(k0+bkk)*Dd + bj + bc4];
    __syncthreads();
#pragma unroll
    for (int kk=0;kk<16;kk++){
      float ar[4], br[4];
#pragma unroll
      for (int r=0;r<4;r++) ar[r]=As[ty*4+r][kk];
#pragma unroll
      for (int c=0;c<4;c++) br[c]=Bs[kk][tx*4+c];
#pragma unroll
      for (int r=0;r<4;r++)
#pragma unroll
        for (int c=0;c<4;c++) acc[r][c]+=ar[r]*br[c];
    }
    __syncthreads();
  }
#pragma unroll
  for (int r=0;r<4;r++)
#pragma unroll
    for (int c=0;c<4;c++){
      if (OH) ((__half*)Cv)[(size_t)(bi+ty*4+r)*Dd + bj+tx*4+c] = __float2half(acc[r][c]);
      else    ((float*)Cv)[(size_t)(bi+ty*4+r)*Dd + bj+tx*4+c] = acc[r][c];
    }
}

__global__ void foldVec(const float* __restrict__ Wqkv, const float* __restrict__ bqkv,
                        const float* __restrict__ Wo, const float* __restrict__ bo){
  int i = threadIdx.x;
  float s1=0.f, s2=0.f, tv=0.f;
  for (int k=0;k<Dd;k++){
    s1 += Wqkv[k*Dd+i]*bqkv[Dd+k];
    s2 += Wqkv[(Dd+k)*Dd+i]*bqkv[k];
    tv += Wo[i*Dd+k]*bqkv[2*Dd+k];
  }
  g_c1[i]=s1; g_c2[i]=s2; g_tvec[i]=tv+bo[i];
  if (i==0){
    float s0=0.f;
    for (int k=0;k<Dd;k++) s0 += bqkv[k]*bqkv[Dd+k];
    g_c0=s0;
  }
}
__global__ void foldBconst(const float* __restrict__ Wout, const float* __restrict__ bout){
  int o = threadIdx.x;
  if (o < OUTC){
    float b=0.f;
    for (int k=0;k<Dd;k++) b += Wout[o*Dd+k]*g_tvec[k];
    g_bconst[o]=b+bout[o];
  }
}

// ---------------- CSR build ----------------
__global__ void count_k(const int* __restrict__ ei){
  int idx = blockIdx.x*256 + threadIdx.x;
  if (idx >= Tt*Ee) return;
  int t = idx / Ee, e = idx - t*Ee;
  int dst = ei[(size_t)t*2*Ee + Ee + e];
  atomicAdd(&g_cnt[t*Nn + dst], 1);
}
__global__ void scan_p1(){
  int bid = blockIdx.x;
  int t = bid/SNB, b = bid - t*SNB;
  const int* cnt = g_cnt + t*Nn + b*SCHUNK;
  __shared__ int sh[256];
  int tid = threadIdx.x;
  int s = 0;
  if (tid < 250){
#pragma unroll
    for (int i=0;i<8;i++) s += cnt[tid*8+i];
  }
  sh[tid]=s; __syncthreads();
  for (int d=128; d; d>>=1){ if (tid<d) sh[tid]+=sh[tid+d]; __syncthreads(); }
  if (tid==0) g_bsum[bid]=sh[0];
}
__global__ void scan_p2(){
  int t = threadIdx.x;
  if (t < Tt){
    int run=0;
    for (int b=0;b<SNB;b++){
      int v = g_bsum[t*SNB+b];
      g_bsum[t*SNB+b] = run;
      run += v;
    }
    g_off[t*(Nn+1)+Nn] = run;
  }
}
__global__ void scan_p3(){
  int bid = blockIdx.x;
  int t = bid/SNB, b = bid - t*SNB;
  int base = t*Nn + b*SCHUNK;
  const int* cnt = g_cnt + base;
  int* off = g_off + t*(Nn+1) + b*SCHUNK;
  int* cur = g_cur + base;
  __shared__ int sh[256];
  int tid = threadIdx.x;
  int vals[8]; int s=0;
  if (tid < 250){
#pragma unroll
    for (int i=0;i<8;i++){ vals[i]=cnt[tid*8+i]; s+=vals[i]; }
  }
  sh[tid]=s; __syncthreads();
  for (int d=1; d<256; d<<=1){
    int v = (tid>=d)? sh[tid-d]:0;
    __syncthreads();
    sh[tid]+=v;
    __syncthreads();
  }
  int run = g_bsum[bid] + ((tid==0)?0:sh[tid-1]);
  if (tid < 250){
#pragma unroll
    for (int i=0;i<8;i++){
      off[tid*8+i]=run; cur[tid*8+i]=run; run += vals[i];
    }
  }
}
__global__ void scatter_k(const int* __restrict__ ei){
  int idx = blockIdx.x*256 + threadIdx.x;
  if (idx >= Tt*Ee) return;
  int t = idx / Ee, e = idx - t*Ee;
  int src = ei[(size_t)t*2*Ee + e];
  int dst = ei[(size_t)t*2*Ee + Ee + e];
  int p = atomicAdd(&g_cur[t*Nn + dst], 1);
  g_srcs[(size_t)t*Ee + p] = src;
}

// ---------------- GAT aggregation: fused es/ed, half2 math, dual accumulators ----------------
template<int MODE>
__global__ __launch_bounds__(256) void gat_agg(const __half* __restrict__ h,
                                               const float* __restrict__ a_s,
                                               const float* __restrict__ a_d,
                                               const float* __restrict__ bias,
                                               const float* __restrict__ gam,
                                               const float* __restrict__ bet,
                                               __half* __restrict__ outh){
  int wg = blockIdx.x*8 + (threadIdx.x>>5);
  if (wg >= TN) return;
  int lane = threadIdx.x & 31;
  int t = wg / Nn;
  int d = wg - t*Nn;
  const int* off  = g_off  + t*(Nn+1);
  const int* srcs = g_srcs + (size_t)t*Ee;
  int tb = t*Nn;

  float asr[8], adr[8];
  __half2 as2[4];
  {
    float4 a = *(const float4*)(a_s + lane*8);
    float4 b = *(const float4*)(a_s + lane*8 + 4);
    asr[0]=a.x; asr[1]=a.y; asr[2]=a.z; asr[3]=a.w;
    asr[4]=b.x; asr[5]=b.y; asr[6]=b.z; asr[7]=b.w;
    float4 c = *(const float4*)(a_d + lane*8);
    float4 e = *(const float4*)(a_d + lane*8 + 4);
    adr[0]=c.x; adr[1]=c.y; adr[2]=c.z; adr[3]=c.w;
    adr[4]=e.x; adr[5]=e.y; adr[6]=e.z; adr[7]=e.w;
#pragma unroll
    for (int q=0;q<4;q++)
      as2[q] = __floats2half2_rn(asr[q*2], asr[q*2+1]);
  }

  __half2 accA[4], accB[4];
  float edv=0.f, s;
  {
    const int4 raw = *(const int4*)(h + (size_t)wg*Dd + lane*8);
    const __half2* hp = (const __half2*)&raw;
    float v[8], es=0.f;
#pragma unroll
    for (int q=0;q<4;q++){
      float2 f = __half22float2(hp[q]);
      v[q*2]=f.x; v[q*2+1]=f.y;
    }
#pragma unroll
    for (int c=0;c<8;c++){ edv += v[c]*adr[c]; es += v[c]*asr[c]; }
    float ev = es + edv;
    float e_self = (ev >= 0.f) ? ev : 0.2f*ev;
    float w0 = __expf(e_self);
    __half2 w0h = __half2half2(__float2half_rn(w0));
#pragma unroll
    for (int q=0;q<4;q++){
      accA[q] = __hmul2(w0h, hp[q]);
      accB[q] = __floats2half2_rn(0.f, 0.f);
    }
    s = w0;
  }

  int beg = off[d], end = off[d+1];
  int j = beg;
  for (; j+3 < end; j += 4){
    int s0 = srcs[j],   s1 = srcs[j+1];
    int s2v = srcs[j+2], s3 = srcs[j+3];
    const int4 r0 = *(const int4*)(h + (size_t)(tb+s0)*Dd + lane*8);
    const int4 r1 = *(const int4*)(h + (size_t)(tb+s1)*Dd + lane*8);
    const int4 r2 = *(const int4*)(h + (size_t)(tb+s2v)*Dd + lane*8);
    const int4 r3 = *(const int4*)(h + (size_t)(tb+s3)*Dd + lane*8);
    const __half2* h0 = (const __half2*)&r0;
    const __half2* h1 = (const __half2*)&r1;
    const __half2* h2 = (const __half2*)&r2;
    const __half2* h3 = (const __half2*)&r3;
    __half2 d0 = __hmul2(h0[0], as2[0]);
    __half2 d1 = __hmul2(h1[0], as2[0]);
    __half2 d2 = __hmul2(h2[0], as2[0]);
    __half2 d3 = __hmul2(h3[0], as2[0]);
#pragma unroll
    for (int q=1;q<4;q++){
      d0 = __hfma2(h0[q], as2[q], d0);
      d1 = __hfma2(h1[q], as2[q], d1);
      d2 = __hfma2(h2[q], as2[q], d2);
      d3 = __hfma2(h3[q], as2[q], d3);
    }
    float e0 = edv + __low2float(d0) + __high2float(d0);
    float e1 = edv + __low2float(d1) + __high2float(d1);
    float e2 = edv + __low2float(d2) + __high2float(d2);
    float e3 = edv + __low2float(d3) + __high2float(d3);
    e0 = (e0 >= 0.f) ? e0 : 0.2f*e0;
    e1 = (e1 >= 0.f) ? e1 : 0.2f*e1;
    e2 = (e2 >= 0.f) ? e2 : 0.2f*e2;
    e3 = (e3 >= 0.f) ? e3 : 0.2f*e3;
    float wA = __expf(e0), wB = __expf(e1), wC = __expf(e2), wD = __expf(e3);
    s += (wA + wB) + (wC + wD);
    __half2 whA = __half2half2(__float2half_rn(wA));
    __half2 whB = __half2half2(__float2half_rn(wB));
    __half2 whC = __half2half2(__float2half_rn(wC));
    __half2 whD = __half2half2(__float2half_rn(wD));
#pragma unroll
    for (int q=0;q<4;q++){
      accA[q] = __hfma2(whA, h0[q], accA[q]);
      accB[q] = __hfma2(whB, h1[q], accB[q]);
      accA[q] = __hfma2(whC, h2[q], accA[q]);
      accB[q] = __hfma2(whD, h3[q], accB[q]);
    }
  }
  for (; j < end; ++j){
    int s0 = srcs[j];
    const int4 r0 = *(const int4*)(h + (size_t)(tb+s0)*Dd + lane*8);
    const __half2* h0 = (const __half2*)&r0;
    __half2 d0 = __hmul2(h0[0], as2[0]);
#pragma unroll
    for (int q=1;q<4;q++) d0 = __hfma2(h0[q], as2[q], d0);
    float e0 = edv + __low2float(d0) + __high2float(d0);
    e0 = (e0 >= 0.f) ? e0 : 0.2f*e0;
    float wA = __expf(e0);
    s += wA;
    __half2 whA = __half2half2(__float2half_rn(wA));
#pragma unroll
    for (int q=0;q<4;q++) accA[q] = __hfma2(whA, h0[q], accA[q]);
  }

  float inv = 1.f/s;
  const float* bp = bias + lane*8;
  float v[8];
#pragma unroll
  for (int q=0;q<4;q++){
    float2 a = __half22float2(accA[q]);
    float2 b = __half22float2(accB[q]);
    v[q*2]   = (a.x + b.x)*inv + bp[q*2];
    v[q*2+1] = (a.y + b.y)*inv + bp[q*2+1];
  }

  if (MODE == 1){
    float sum=0.f;
#pragma unroll
    for (int c=0;c<8;c++) sum += v[c];
    sum = warp_sum(sum);
    float mu = sum*(1.f/Dd);
    float d2s=0.f;
#pragma unroll
    for (int c=0;c<8;c++){ float dd=v[c]-mu; d2s += dd*dd; }
    d2s = warp_sum(d2s);
    float invs = rsqrtf(d2s*(1.f/Dd) + LN_EPS);
    const float* gp = gam + lane*8;
    const float* btp = bet + lane*8;
#pragma unroll
    for (int c=0;c<8;c++){
      float y = (v[c]-mu)*invs*gp[c] + btp[c];
      v[c] = fmaxf(y, 0.f);
    }
  }
  __half* op = outh + (size_t)wg*Dd + lane*8;
  __half2 o[4];
#pragma unroll
  for (int q=0;q<4;q++) o[q] = __float22half2_rn(make_float2(v[q*2], v[q*2+1]));
  *(int4*)op = *(int4*)o;
}

// ---------------- temporal attention (fp16 emb) ----------------
__global__ __launch_bounds__(256) void temporal_kernel(){
  int n = blockIdx.x*8 + (threadIdx.x>>5);
  if (n >= Nn) return;
  int lane = threadIdx.x & 31;
  float er[8][8];
#pragma unroll
  for (int s2=0;s2<8;s2++){
    const int4 raw = *(const int4*)(g_embh + ((size_t)s2*Nn + n)*Dd + lane*8);
    const __half2* hp = (const __half2*)&raw;
#pragma unroll
    for (int q=0;q<4;q++){
      float2 f = __half22float2(hp[q]);
      er[s2][q*2]=f.x; er[s2][q*2+1]=f.y;
    }
  }
  float uc[8], c1r[8];
  {
    const float* pu = g_u + (size_t)n*Dd + lane*8;
    float4 a=*(const float4*)pu, b=*(const float4*)(pu+4);
    const float* pc2 = g_c2 + lane*8;
    float4 ca=*(const float4*)pc2, cb=*(const float4*)(pc2+4);
    uc[0]=a.x+ca.x; uc[1]=a.y+ca.y; uc[2]=a.z+ca.z; uc[3]=a.w+ca.w;
    uc[4]=b.x+cb.x; uc[5]=b.y+cb.y; uc[6]=b.z+cb.z; uc[7]=b.w+cb.w;
    const float* pc1 = g_c1 + lane*8;
    float4 da=*(const float4*)pc1, db=*(const float4*)(pc1+4);
    c1r[0]=da.x; c1r[1]=da.y; c1r[2]=da.z; c1r[3]=da.w;
    c1r[4]=db.x; c1r[5]=db.y; c1r[6]=db.z; c1r[7]=db.w;
  }
  float t1p=0.f;
#pragma unroll
  for (int c=0;c<8;c++) t1p += c1r[c]*er[7][c];
  float t1 = warp_sum(t1p) + g_c0;
  float sc[8];
#pragma unroll
  for (int s2=0;s2<8;s2++){
    float p=0.f;
#pragma unroll
    for (int c=0;c<8;c++) p += uc[c]*er[s2][c];
    sc[s2] = (warp_sum(p) + t1) * 0.0625f;
  }
  float mx = sc[0];
#pragma unroll
  for (int s2=1;s2<8;s2++) mx = fmaxf(mx, sc[s2]);
  float w[8]; float den=0.f;
#pragma unroll
  for (int s2=0;s2<8;s2++){ w[s2]=__expf(sc[s2]-mx); den+=w[s2]; }
  float inv = 1.f/den;
  float xb[8];
#pragma unroll
  for (int c=0;c<8;c++){
    float a=0.f;
#pragma unroll
    for (int s2=0;s2<8;s2++) a += w[s2]*er[s2][c];
    xb[c]=a*inv;
  }
  __half* po = g_xbarh + (size_t)n*Dd + lane*8;
  __half2 o[4];
#pragma unroll
  for (int q=0;q<4;q++) o[q] = __float22half2_rn(make_float2(xb[q*2], xb[q*2+1]));
  *(int4*)po = *(int4*)o;
}

// ---------------- BatchNorm stats ----------------
__global__ void bn_part(){
  __shared__ float ss[256], sq[256];
  int col = threadIdx.x & 63;
  int rg  = threadIdx.x >> 6;
  float s=0.f, q=0.f;
  for (int n = blockIdx.x*4 + rg; n < Nn; n += 1024){
    float v = g_logits[(size_t)n*OUTC + col];
    s += v; q += v*v;
  }
  ss[threadIdx.x]=s; sq[threadIdx.x]=q;
  __syncthreads();
  if (rg==0){
    for (int r2=1;r2<4;r2++){ s += ss[r2*64+col]; q += sq[r2*64+col]; }
    g_psum[blockIdx.x*64+col]=s;
    g_psq [blockIdx.x*64+col]=q;
  }
}
__global__ void bn_final(){
  int col = threadIdx.x;
  float s=0.f, q=0.f;
  for (int b=0;b<256;b++){ s += g_psum[b*64+col]; q += g_psq[b*64+col]; }
  float mu = s/(float)Nn;
  g_mu[col]=mu;
  g_var[col]=q/(float)Nn - mu*mu;
}

// ---------------- BN apply + log_softmax ----------------
__global__ __launch_bounds__(256) void out_kernel(const float* __restrict__ bn_g,
                                                  const float* __restrict__ bn_b,
                                                  float* __restrict__ out){
  int n = blockIdx.x*8 + (threadIdx.x>>5);
  if (n >= Nn) return;
  int lane = threadIdx.x & 31;
  int c0 = lane, c1i = lane + 32;
  float y0 = (g_logits[(size_t)n*OUTC + c0]  - g_mu[c0]) * rsqrtf(g_var[c0]+LN_EPS)*bn_g[c0]+bn_b[c0];
  float y1 = (g_logits[(size_t)n*OUTC + c1i] - g_mu[c1i])* rsqrtf(g_var[c1i]+LN_EPS)*bn_g[c1i]+bn_b[c1i];
  float mx = warp_max(fmaxf(y0,y1));
  float se = warp_sum(__expf(y0-mx) + __expf(y1-mx));
  float l  = mx + logf(se);
  out[(size_t)n*OUTC + c0]  = y0 - l;
  out[(size_t)n*OUTC + c1i] = y1 - l;
}

// ---------------- orchestration ----------------
extern "C" void kernel_launch(void* const* d_in, const int* in_sizes, int n_in,
                              void* d_out, int out_size) {
  const float* feats = (const float*)d_in[0];
  const int*   ei    = (const int*)  d_in[1];
  const float* W1    = (const float*)d_in[2];
  const float* a_s1  = (const float*)d_in[3];
  const float* a_d1  = (const float*)d_in[4];
  const float* b1    = (const float*)d_in[5];
  const float* W2    = (const float*)d_in[6];
  const float* a_s2  = (const float*)d_in[7];
  const float* a_d2  = (const float*)d_in[8];
  const float* b2    = (const float*)d_in[9];
  const float* ln_g  = (const float*)d_in[10];
  const float* ln_b  = (const float*)d_in[11];
  const float* Wqkv  = (const float*)d_in[12];
  const float* bqkv  = (const float*)d_in[13];
  const float* Wo    = (const float*)d_in[14];
  const float* bo    = (const float*)d_in[15];
  const float* Wout  = (const float*)d_in[16];
  const float* bout  = (const float*)d_in[17];
  const float* bn_g  = (const float*)d_in[18];
  const float* bn_b  = (const float*)d_in[19];
  float* out = (float*)d_out;

  __half *p_h, *p_x1h, *p_embh, *p_feats16, *p_W1h, *p_W2h, *p_Mh, *p_Ph, *p_xbarh;
  float *p_bconst, *p_u, *p_logits, *p_R;
  int *p_cnt;
  cudaGetSymbolAddress((void**)&p_h,       g_h);
  cudaGetSymbolAddress((void**)&p_x1h,     g_x1h);
  cudaGetSymbolAddress((void**)&p_embh,    g_embh);
  cudaGetSymbolAddress((void**)&p_feats16, g_feats16);
  cudaGetSymbolAddress((void**)&p_W1h,     g_W1h);
  cudaGetSymbolAddress((void**)&p_W2h,     g_W2h);
  cudaGetSymbolAddress((void**)&p_Mh,      g_Mh);
  cudaGetSymbolAddress((void**)&p_Ph,      g_Ph);
  cudaGetSymbolAddress((void**)&p_bconst,  g_bconst);
  cudaGetSymbolAddress((void**)&p_u,       g_u);
  cudaGetSymbolAddress((void**)&p_xbarh,   g_xbarh);
  cudaGetSymbolAddress((void**)&p_logits,  g_logits);
  cudaGetSymbolAddress((void**)&p_R,       g_R);
  cudaGetSymbolAddress((void**)&p_cnt,     g_cnt);

  cudaFuncSetAttribute(gemm_hf<0>, cudaFuncAttributeMaxDynamicSharedMemorySize, GEMM_SMEM);
  cudaFuncSetAttribute(gemm_hf<1>, cudaFuncAttributeMaxDynamicSharedMemorySize, GEMM_SMEM);

  // side stream for CSR + fold chains (graph-capture fork/join via events)
  cudaStream_t s2;
  cudaEvent_t evFork, evJoin1, evJoin2;
  cudaStreamCreateWithFlags(&s2, cudaStreamNonBlocking);
  cudaEventCreateWithFlags(&evFork,  cudaEventDisableTiming);
  cudaEventCreateWithFlags(&evJoin1, cudaEventDisableTiming);
  cudaEventCreateWithFlags(&evJoin2, cudaEventDisableTiming);

  cudaEventRecord(evFork, 0);
  cudaStreamWaitEvent(s2, evFork, 0);

  // --- side stream: CSR build, then MHA folds ---
  cudaMemsetAsync(p_cnt, 0, TN*sizeof(int), s2);
  count_k<<<(Tt*Ee+255)/256,256,0,s2>>>(ei);
  scan_p1<<<Tt*SNB,256,0,s2>>>();
  scan_p2<<<1,32,0,s2>>>();
  scan_p3<<<Tt*SNB,256,0,s2>>>();
  scatter_k<<<(Tt*Ee+255)/256,256,0,s2>>>(ei);
  cudaEventRecord(evJoin1, s2);
  foldM<<<dim3(4,4),256,0,s2>>>(Wqkv);
  foldNN<0><<<dim3(4,4),256,0,s2>>>(Wo, Wqkv + 2*Dd*Dd, p_R);
  foldNN<1><<<dim3(4,1),256,0,s2>>>(Wout, p_R, p_Ph);
  foldVec<<<1,256,0,s2>>>(Wqkv, bqkv, Wo, bo);
  foldBconst<<<1,64,0,s2>>>(Wout, bout);
  cudaEventRecord(evJoin2, s2);

  // --- main stream: converts + GEMM1 ---
  f2h<<<(TN*Fin/4+255)/256,256>>>(feats, p_feats16, TN*Fin/4);
  f2h<<<(Dd*Fin/4+255)/256,256>>>(W1, p_W1h, Dd*Fin/4);
  f2h<<<(Dd*Dd/4+255)/256,256>>>(W2, p_W2h, Dd*Dd/4);
  {
    dim3 grid(Dd/BN, TN/BM);
    gemm_hf<1><<<grid,256,GEMM_SMEM>>>(TN, Fin, Dd, p_feats16, p_W1h, nullptr, p_h);
  }

  // join 1: CSR ready
  cudaStreamWaitEvent(0, evJoin1, 0);
  gat_agg<0><<<TN/8,256>>>(p_h, a_s1, a_d1, b1, nullptr, nullptr, p_x1h);

  // GAT layer 2
  {
    dim3 grid(Dd/BN, TN/BM);
    gemm_hf<1><<<grid,256,GEMM_SMEM>>>(TN, Dd, Dd, p_x1h, p_W2h, nullptr, p_h);
  }
  gat_agg<1><<<TN/8,256>>>(p_h, a_s2, a_d2, b2, ln_g, ln_b, p_embh);

  // join 2: folds ready
  cudaStreamWaitEvent(0, evJoin2, 0);

  // temporal attention (collapsed): u = emb7 @ M
  {
    dim3 grid(Dd/BN, (Nn+BM-1)/BM);
    gemm_hf<0><<<grid,256,GEMM_SMEM>>>(Nn, Dd, Dd, p_embh + (size_t)7*Nn*Dd, p_Mh, nullptr, p_u);
  }
  temporal_kernel<<<(Nn+7)/8,256>>>();

  // logits = xbar @ P^T + bconst
  {
    dim3 grid(1, (Nn+BM-1)/BM);
    gemm_hf<0><<<grid,256,GEMM_SMEM>>>(Nn, Dd, OUTC, p_xbarh, p_Ph, p_bconst, p_logits);
  }

  bn_part<<<256,256>>>();
  bn_final<<<1,64>>>();
  out_kernel<<<(Nn+7)/8,256>>>(bn_g, bn_b, out);

  cudaStreamDestroy(s2);
  cudaEventDestroy(evFork);
  cudaEventDestroy(evJoin1);
  cudaEventDestroy(evJoin2);
}